// round 8
// baseline (speedup 1.0000x reference)
#include <cuda_runtime.h>
#include <math.h>

#define Bn 32
#define N1 512
#define N2 512
#define Dd 128
#define Mw 256
#define Kd 96
#define BARRIERc 10000.0f

#define IG2 14.4269504088896f   /* log2(e)/gamma */
#define GLN2 0.069314718055995f /* gamma*ln(2)   */
#define INFf __int_as_float(0x7f800000)
#define FULLM 0xffffffffu

__device__ float g_T1[Bn], g_T2[Bn];
__device__ float g_node[Bn][Mw][Kd];
__device__ float g_alpha[Bn][Mw][Kd];
__device__ float g_beta[Bn][Mw][Kd];

__device__ __forceinline__ float ex2a(float x) { float y; asm("ex2.approx.f32 %0, %1;" : "=f"(y) : "f"(x)); return y; }
__device__ __forceinline__ float lg2a(float x) { float y; asm("lg2.approx.f32 %0, %1;" : "=f"(y) : "f"(x)); return y; }
__device__ __forceinline__ float sqrta(float x) { float y; asm("sqrt.approx.f32 %0, %1;" : "=f"(y) : "f"(x)); return y; }

__device__ __forceinline__ unsigned f2o(float x) {
    unsigned u = __float_as_uint(x);
    return (u & 0x80000000u) ? ~u : (u | 0x80000000u);
}
__device__ __forceinline__ float o2f(unsigned v) {
    return __uint_as_float((v & 0x80000000u) ? (v ^ 0x80000000u) : ~v);
}

// ---------------- kernel 0 ----------------
__global__ void k0_maxes(const float* __restrict__ t1, const float* __restrict__ t2) {
    int b = blockIdx.x, t = threadIdx.x;
    float m1 = -3.4e38f, m2 = -3.4e38f;
    for (int i = t; i < N1; i += 256) m1 = fmaxf(m1, t1[b * N1 + i]);
    for (int i = t; i < N2; i += 256) m2 = fmaxf(m2, t2[b * N2 + i]);
    __shared__ float s1[8], s2[8];
    for (int o = 16; o; o >>= 1) {
        m1 = fmaxf(m1, __shfl_xor_sync(FULLM, m1, o));
        m2 = fmaxf(m2, __shfl_xor_sync(FULLM, m2, o));
    }
    if ((t & 31) == 0) { s1[t >> 5] = m1; s2[t >> 5] = m2; }
    __syncthreads();
    if (t == 0) {
        float a = s1[0], c = s2[0];
        for (int w = 1; w < 8; w++) { a = fmaxf(a, s1[w]); c = fmaxf(c, s2[w]); }
        g_T1[b] = a; g_T2[b] = c;
    }
}

// ---------------- kernel 2: node costs (fused s1 interp + smem staging) ----------------
__global__ void k2_node(const float* __restrict__ s1f, const float* __restrict__ s2f,
                        const float* __restrict__ glb_lb, const float* __restrict__ glb_ub,
                        const float* __restrict__ tw) {
    int b = blockIdx.y;
    int tid = threadIdx.x;
    int wq = tid >> 5, lane = tid & 31;
    int k = blockIdx.x * 8 + wq;
    __shared__ float s_lb[Mw], s_w[Mw], s_tw[Mw];
    __shared__ int   s_i0[32];
    __shared__ float s_w1[32];
    __shared__ float4 s_s1[32][32];
    float T2 = g_T2[b], T1 = g_T1[b];
    for (int i = tid; i < Mw; i += 256) {
        float lb = glb_lb[b * Mw + i] * T2;
        float ub = glb_ub[b * Mw + i] * T2;
        s_lb[i] = lb; s_w[i] = ub - lb; s_tw[i] = tw[b * Mw + i];
    }
    __syncthreads();
    float frk = (float)k / 95.0f;
    float invT2 = 1.f / T2, invT1 = 1.f / T1;
    const float* s2b = s2f + (size_t)b * N2 * Dd;
    const float* s1b = s1f + (size_t)b * N1 * Dd;
    int i0p = -1;
    float4 f0v = make_float4(0.f, 0.f, 0.f, 0.f), f1v = f0v;
    for (int mc = 0; mc < Mw; mc += 32) {
        __syncthreads();
        if (tid < 32) {
            float pos = s_tw[mc + tid] * invT1;
            float x = fminf(fmaxf(pos, 0.f), 1.f) * (float)(N1 - 1);
            int i0 = min(max((int)x, 0), N1 - 2);
            s_i0[tid] = i0;
            s_w1[tid] = x - (float)i0;
        }
        __syncthreads();
        for (int idx = tid; idx < 1024; idx += 256) {
            int ml = idx >> 5, l4 = idx & 31;
            const float4* r0 = (const float4*)(s1b + (size_t)s_i0[ml] * Dd);
            float4 f0 = r0[l4], f1 = r0[32 + l4];
            float ww = s_w1[ml];
            float4 o;
            o.x = f0.x + ww * (f1.x - f0.x);
            o.y = f0.y + ww * (f1.y - f0.y);
            o.z = f0.z + ww * (f1.z - f0.z);
            o.w = f0.w + ww * (f1.w - f0.w);
            s_s1[ml][l4] = o;
        }
        __syncthreads();
        for (int m0 = 0; m0 < 32; m0 += 4) {
            float acc[4], tks[4];
            #pragma unroll
            for (int u = 0; u < 4; u++) {
                int m = mc + m0 + u;
                float tk = s_lb[m] + s_w[m] * frk;
                tks[u] = tk;
                float x = fminf(fmaxf(tk * invT2, 0.f), 1.f) * (float)(N2 - 1);
                int i0 = min(max((int)x, 0), N2 - 2);
                float w = x - (float)i0;
                if (i0 != i0p) {
                    f0v = *((const float4*)(s2b + (size_t)i0 * Dd) + lane);
                    f1v = *((const float4*)(s2b + (size_t)(i0 + 1) * Dd) + lane);
                    i0p = i0;
                }
                float4 s1v = s_s1[m0 + u][lane];
                float d0 = s1v.x - (f0v.x + w * (f1v.x - f0v.x));
                float d1 = s1v.y - (f0v.y + w * (f1v.y - f0v.y));
                float d2 = s1v.z - (f0v.z + w * (f1v.z - f0v.z));
                float d3 = s1v.w - (f0v.w + w * (f1v.w - f0v.w));
                acc[u] = fmaf(d0, d0, fmaf(d1, d1, fmaf(d2, d2, d3 * d3)));
            }
            for (int o = 16; o; o >>= 1) {
                #pragma unroll
                for (int u = 0; u < 4; u++)
                    acc[u] += __shfl_xor_sync(FULLM, acc[u], o);
            }
            if (lane == 0) {
                #pragma unroll
                for (int u = 0; u < 4; u++) {
                    int m = mc + m0 + u;
                    float twm = s_tw[m];
                    float wt = 0.f;
                    if (m > 0) wt += twm - s_tw[m - 1];
                    if (m < Mw - 1) wt += s_tw[m + 1] - twm;
                    wt *= 0.5f;
                    float node = acc[u] * wt;
                    float tk = tks[u];
                    if (m == 0) node += BARRIERc * tk * tk;
                    if (m == Mw - 1) { float dd = tk - T2; node += BARRIERc * dd * dd; }
                    g_node[b][m][k] = node;
                }
            }
        }
    }
}

// ---------------- edge cost ----------------
__device__ __forceinline__ float edge_fn(float slope, float gub, float rwd) {
    float d1 = slope - 1.f;
    float n1 = fminf(slope, 0.f);
    float r2 = fmaxf(slope - gub, 0.f);
    float pen = fmaf(n1, n1, r2 * r2);
    return fmaf(BARRIERc, pen, rwd * d1 * d1);
}

// general windowed softmin (cold path)
__device__ __forceinline__ float softmin_win(
    const float* __restrict__ sa, const float* __restrict__ sfrac,
    int jlo, int jhi, float tref, float sgn, float invd,
    float lbp, float wp, float gub, float rwd) {
    float mval = INFf, ssum = 0.f;
    for (int j = jlo; j <= jhi; j++) {
        float tpj = lbp + wp * sfrac[j];
        float slope = sgn * (tref - tpj) * invd;
        float e = edge_fn(slope, gub, rwd);
        float xv = sa[j] + e;
        float dlt = xv - mval;
        float tt = ex2a(-fabsf(dlt) * IG2);
        if (dlt < 0.f) { ssum = fmaf(ssum, tt, 1.f); mval = xv; }
        else           { ssum += tt; }
    }
    return mval - GLN2 * lg2a(ssum);
}

// 2-candidate softmin (y may be INF)
__device__ __forceinline__ float sm2(float x, float y) {
    float mv = fminf(x, y);
    float ss = 1.f + ex2a(-fabsf(x - y) * IG2);
    return mv - GLN2 * lg2a(ss);
}

// ---------------- kernel 3: single-warp scans, post-pass verification ----------------
// layout: lane holds k = 3*lane + r
__global__ void k3_scan(const float* __restrict__ tw, const float* __restrict__ reg_wt,
                        const float* __restrict__ lgu, const float* __restrict__ glb_lb,
                        const float* __restrict__ glb_ub) {
    int dir = blockIdx.x, b = blockIdx.y;
    int lane = threadIdx.x;
    __shared__ float s_lb[Mw], s_w[Mw], s_tw[Mw], s_frac[Kd], s_a[Kd];
    float T2 = g_T2[b];
    for (int i = lane; i < Mw; i += 32) {
        float lb = glb_lb[b * Mw + i] * T2;
        float ub = glb_ub[b * Mw + i] * T2;
        s_lb[i] = lb; s_w[i] = ub - lb; s_tw[i] = tw[b * Mw + i];
    }
    for (int i = lane; i < Kd; i += 32) s_frac[i] = (float)i / 95.0f;
    __syncwarp();
    float rw = reg_wt[b], gub = lgu[b];
    float gmin1 = fmaxf(1.f, gub);
    int kb = 3 * lane;
    float fr0 = (float)kb / 95.0f, fr1 = (float)(kb + 1) / 95.0f, fr2 = (float)(kb + 2) / 95.0f;
    bool gl = (lane >= 1), gr = (lane <= 30);

    if (dir == 0) {
        // ======== forward fast path: pure value chain ========
        {
            float a0 = g_node[b][0][kb], a1 = g_node[b][0][kb + 1], a2 = g_node[b][0][kb + 2];
            g_alpha[b][0][kb] = a0; g_alpha[b][0][kb + 1] = a1; g_alpha[b][0][kb + 2] = a2;
            float nn0 = g_node[b][1][kb], nn1 = g_node[b][1][kb + 1], nn2 = g_node[b][1][kb + 2];
            int i2 = min(2, Mw - 1);
            float nf0 = g_node[b][i2][kb], nf1 = g_node[b][i2][kb + 1], nf2 = g_node[b][i2][kb + 2];
            float twp = s_tw[0];
            for (int i = 0; i < Mw - 1; i++) {
                float twn = s_tw[i + 1];
                float dtw = twn - twp;
                float invd = __fdividef(1.f, dtw);
                float rwd = rw * dtw;
                int ip = min(i + 3, Mw - 1);
                float nl0 = g_node[b][ip][kb], nl1 = g_node[b][ip][kb + 1], nl2 = g_node[b][ip][kb + 2];
                float sinv = s_w[i] * invd * (1.0f / 95.0f);
                float e2 = edge_fn(sinv, gub, rwd);   // delta=1
                float p2 = __shfl_up_sync(FULLM, a2, 1);
                float an0 = nn0 + sm2(a0 + rwd, gl ? p2 + e2 : INFf);
                float an1 = nn1 + sm2(a1 + rwd, a0 + e2);
                float an2 = nn2 + sm2(a2 + rwd, a1 + e2);
                g_alpha[b][i + 1][kb] = an0; g_alpha[b][i + 1][kb + 1] = an1; g_alpha[b][i + 1][kb + 2] = an2;
                a0 = an0; a1 = an1; a2 = an2;
                nn0 = nf0; nn1 = nf1; nn2 = nf2;
                nf0 = nl0; nf1 = nl1; nf2 = nl2;
                twp = twn;
            }
        }
        // ======== verification post-pass (independent iterations) ========
        bool allok = (gub >= 0.f);
        for (int i = 0; i < Mw - 1; i++) {
            float v0 = g_alpha[b][i][kb], v1 = g_alpha[b][i][kb + 1], v2 = g_alpha[b][i][kb + 2];
            float dtw = s_tw[i + 1] - s_tw[i];
            float wp = s_w[i];
            float rwd = rw * dtw;
            float sinv = wp * __fdividef(1.f, dtw) * (1.0f / 95.0f);
            float mina = o2f(__reduce_min_sync(FULLM, f2o(fminf(fminf(v0, v1), v2))));
            float maxa = o2f(__reduce_max_sync(FULLM, f2o(fmaxf(fmaxf(v0, v1), v2))));
            float thr = maxa - mina + 15.f + rwd;
            bool ok = (s_lb[i + 1] == s_lb[i]) && (s_w[i + 1] == wp) && (wp > 0.f)
                   && (edge_fn(-sinv, gub, rwd) >= thr)
                   && (edge_fn(2.f * sinv, gub, rwd) >= thr)
                   && (2.f * sinv >= gmin1);
            allok = allok && ok;
        }
        // ======== cold general redo ========
        if (!__all_sync(FULLM, allok)) {
            float a0 = g_node[b][0][kb], a1 = g_node[b][0][kb + 1], a2 = g_node[b][0][kb + 2];
            g_alpha[b][0][kb] = a0; g_alpha[b][0][kb + 1] = a1; g_alpha[b][0][kb + 2] = a2;
            float mina = o2f(__reduce_min_sync(FULLM, f2o(fminf(fminf(a0, a1), a2))));
            float maxa = o2f(__reduce_max_sync(FULLM, f2o(fmaxf(fmaxf(a0, a1), a2))));
            float lbp = s_lb[0], wp = s_w[0], twp = s_tw[0];
            for (int i = 0; i < Mw - 1; i++) {
                float lbn = s_lb[i + 1], wn = s_w[i + 1], twn = s_tw[i + 1];
                float dtw = twn - twp;
                float invd = __fdividef(1.f, dtw);
                float rwd = rw * dtw;
                s_a[kb] = a0; s_a[kb + 1] = a1; s_a[kb + 2] = a2;
                __syncwarp();
                float marg = sqrta((maxa - mina + 16.f) * (1.f / BARRIERc));
                float inv95wp = __fdividef(95.0f, wp);
                bool degen = !(wp > 0.f);
                float loOff = (gub + marg) * dtw;
                float hiOff = marg * dtw;
                float res[3];
                float frs[3] = {fr0, fr1, fr2};
                #pragma unroll
                for (int r = 0; r < 3; r++) {
                    float tnk = lbn + wn * frs[r];
                    int jlo = max(0, __float2int_ru((tnk - loOff - lbp) * inv95wp));
                    int jhi = min(Kd - 1, __float2int_rd((tnk + hiOff - lbp) * inv95wp));
                    if (degen) { jlo = 0; jhi = Kd - 1; }
                    if (jhi < jlo) { int c = min(Kd - 1, max(0, jlo)); jlo = max(0, c - 1); jhi = min(Kd - 1, c + 1); }
                    res[r] = softmin_win(s_a, s_frac, jlo, jhi, tnk, 1.f, invd, lbp, wp, gub, rwd);
                }
                __syncwarp();
                float an0 = g_node[b][i + 1][kb] + res[0];
                float an1 = g_node[b][i + 1][kb + 1] + res[1];
                float an2 = g_node[b][i + 1][kb + 2] + res[2];
                g_alpha[b][i + 1][kb] = an0; g_alpha[b][i + 1][kb + 1] = an1; g_alpha[b][i + 1][kb + 2] = an2;
                mina = o2f(__reduce_min_sync(FULLM, f2o(fminf(fminf(an0, an1), an2))));
                maxa = o2f(__reduce_max_sync(FULLM, f2o(fmaxf(fmaxf(an0, an1), an2))));
                a0 = an0; a1 = an1; a2 = an2;
                lbp = lbn; wp = wn; twp = twn;
            }
        }
    } else {
        // ======== backward fast path ========
        {
            float a0 = g_node[b][Mw - 1][kb], a1 = g_node[b][Mw - 1][kb + 1], a2 = g_node[b][Mw - 1][kb + 2];
            g_beta[b][Mw - 1][kb] = 0.f; g_beta[b][Mw - 1][kb + 1] = 0.f; g_beta[b][Mw - 1][kb + 2] = 0.f;
            float ni0 = g_node[b][Mw - 2][kb], ni1 = g_node[b][Mw - 2][kb + 1], ni2 = g_node[b][Mw - 2][kb + 2];
            int i3 = max(Mw - 3, 0);
            float nf0 = g_node[b][i3][kb], nf1 = g_node[b][i3][kb + 1], nf2 = g_node[b][i3][kb + 2];
            float twp = s_tw[Mw - 1];
            for (int i = Mw - 2; i >= 0; i--) {
                float twj = s_tw[i];
                float dtw = twp - twj;
                float invd = __fdividef(1.f, dtw);
                float rwd = rw * dtw;
                int ip = max(i - 2, 0);
                float nl0 = g_node[b][ip][kb], nl1 = g_node[b][ip][kb + 1], nl2 = g_node[b][ip][kb + 2];
                float sinv = s_w[i + 1] * invd * (1.0f / 95.0f);
                float e2 = edge_fn(sinv, gub, rwd);
                float n0 = __shfl_down_sync(FULLM, a0, 1);
                float bn0 = sm2(a0 + rwd, a1 + e2);
                float bn1 = sm2(a1 + rwd, a2 + e2);
                float bn2 = sm2(a2 + rwd, gr ? n0 + e2 : INFf);
                g_beta[b][i][kb] = bn0; g_beta[b][i][kb + 1] = bn1; g_beta[b][i][kb + 2] = bn2;
                a0 = ni0 + bn0; a1 = ni1 + bn1; a2 = ni2 + bn2;
                ni0 = nf0; ni1 = nf1; ni2 = nf2;
                nf0 = nl0; nf1 = nl1; nf2 = nl2;
                twp = twj;
            }
        }
        // ======== verification post-pass ========
        bool allok = (gub >= 0.f);
        for (int i = Mw - 2; i >= 0; i--) {
            int ii = i + 1;
            float v0 = g_node[b][ii][kb] + g_beta[b][ii][kb];
            float v1 = g_node[b][ii][kb + 1] + g_beta[b][ii][kb + 1];
            float v2 = g_node[b][ii][kb + 2] + g_beta[b][ii][kb + 2];
            float dtw = s_tw[ii] - s_tw[i];
            float wp = s_w[ii];
            float rwd = rw * dtw;
            float sinv = wp * __fdividef(1.f, dtw) * (1.0f / 95.0f);
            float mina = o2f(__reduce_min_sync(FULLM, f2o(fminf(fminf(v0, v1), v2))));
            float maxa = o2f(__reduce_max_sync(FULLM, f2o(fmaxf(fmaxf(v0, v1), v2))));
            float thr = maxa - mina + 15.f + rwd;
            bool ok = (s_lb[i] == s_lb[ii]) && (s_w[i] == wp) && (wp > 0.f)
                   && (edge_fn(-sinv, gub, rwd) >= thr)
                   && (edge_fn(2.f * sinv, gub, rwd) >= thr)
                   && (2.f * sinv >= gmin1);
            allok = allok && ok;
        }
        // ======== cold general redo ========
        if (!__all_sync(FULLM, allok)) {
            float a0 = g_node[b][Mw - 1][kb], a1 = g_node[b][Mw - 1][kb + 1], a2 = g_node[b][Mw - 1][kb + 2];
            g_beta[b][Mw - 1][kb] = 0.f; g_beta[b][Mw - 1][kb + 1] = 0.f; g_beta[b][Mw - 1][kb + 2] = 0.f;
            float mina = o2f(__reduce_min_sync(FULLM, f2o(fminf(fminf(a0, a1), a2))));
            float maxa = o2f(__reduce_max_sync(FULLM, f2o(fmaxf(fmaxf(a0, a1), a2))));
            float lbp = s_lb[Mw - 1], wp = s_w[Mw - 1], twp = s_tw[Mw - 1];
            for (int i = Mw - 2; i >= 0; i--) {
                float lbj = s_lb[i], wj = s_w[i], twj = s_tw[i];
                float dtw = twp - twj;
                float invd = __fdividef(1.f, dtw);
                float rwd = rw * dtw;
                s_a[kb] = a0; s_a[kb + 1] = a1; s_a[kb + 2] = a2;
                __syncwarp();
                float marg = sqrta((maxa - mina + 16.f) * (1.f / BARRIERc));
                float inv95wp = __fdividef(95.0f, wp);
                bool degen = !(wp > 0.f);
                float loOff = marg * dtw;
                float hiOff = (gub + marg) * dtw;
                float res[3];
                float frs[3] = {fr0, fr1, fr2};
                #pragma unroll
                for (int r = 0; r < 3; r++) {
                    float tj = lbj + wj * frs[r];
                    int klo = max(0, __float2int_ru((tj - loOff - lbp) * inv95wp));
                    int khi = min(Kd - 1, __float2int_rd((tj + hiOff - lbp) * inv95wp));
                    if (degen) { klo = 0; khi = Kd - 1; }
                    if (khi < klo) { int cc = min(Kd - 1, max(0, klo)); klo = max(0, cc - 1); khi = min(Kd - 1, cc + 1); }
                    res[r] = softmin_win(s_a, s_frac, klo, khi, tj, -1.f, invd, lbp, wp, gub, rwd);
                }
                __syncwarp();
                g_beta[b][i][kb] = res[0]; g_beta[b][i][kb + 1] = res[1]; g_beta[b][i][kb + 2] = res[2];
                float c0 = g_node[b][i][kb] + res[0];
                float c1 = g_node[b][i][kb + 1] + res[1];
                float c2 = g_node[b][i][kb + 2] + res[2];
                mina = o2f(__reduce_min_sync(FULLM, f2o(fminf(fminf(c0, c1), c2))));
                maxa = o2f(__reduce_max_sync(FULLM, f2o(fmaxf(fmaxf(c0, c1), c2))));
                a0 = c0; a1 = c1; a2 = c2;
                lbp = lbj; wp = wj; twp = twj;
            }
        }
    }
}

// ---------------- kernel 4: 8 warps/block ----------------
__global__ void k4_out(const float* __restrict__ glb_lb, const float* __restrict__ glb_ub,
                       float* __restrict__ out) {
    int b = blockIdx.y;
    int wid = threadIdx.x >> 5, lane = threadIdx.x & 31;
    int m = blockIdx.x * 8 + wid;
    float T2 = g_T2[b];
    float lb = glb_lb[b * Mw + m] * T2;
    float ub = glb_ub[b * Mw + m] * T2;
    float w = ub - lb;
    float v[3], ta[3];
    #pragma unroll
    for (int r = 0; r < 3; r++) {
        int k = lane + 32 * r;
        v[r] = g_alpha[b][m][k] + g_beta[b][m][k];
        ta[r] = lb + w * ((float)k / 95.0f);
    }
    float l = fminf(fminf(v[0], v[1]), v[2]);
    float vmin = o2f(__reduce_min_sync(FULLM, f2o(l)));
    float ps = 0.f, pts = 0.f;
    #pragma unroll
    for (int r = 0; r < 3; r++) {
        float p = ex2a((vmin - v[r]) * IG2);
        ps += p;
        pts = fmaf(p, ta[r], pts);
    }
    for (int o = 16; o; o >>= 1) {
        ps += __shfl_xor_sync(FULLM, ps, o);
        pts += __shfl_xor_sync(FULLM, pts, o);
    }
    if (lane == 0) out[b * Mw + m] = pts / ps;
}

extern "C" void kernel_launch(void* const* d_in, const int* in_sizes, int n_in,
                              void* d_out, int out_size) {
    const float* s1f    = (const float*)d_in[0];
    const float* s2f    = (const float*)d_in[1];
    const float* regw   = (const float*)d_in[2];
    const float* glb_lb = (const float*)d_in[3];
    const float* glb_ub = (const float*)d_in[4];
    const float* lgu    = (const float*)d_in[5];
    const float* t1     = (const float*)d_in[6];
    const float* t2     = (const float*)d_in[7];
    const float* twf    = (const float*)d_in[8];
    float* out = (float*)d_out;

    k0_maxes<<<Bn, 256>>>(t1, t2);
    k2_node<<<dim3(Kd / 8, Bn), 256>>>(s1f, s2f, glb_lb, glb_ub, twf);
    k3_scan<<<dim3(2, Bn), 32>>>(twf, regw, lgu, glb_lb, glb_ub);
    k4_out<<<dim3(Mw / 8, Bn), 256>>>(glb_lb, glb_ub, out);
}

// round 9
// speedup vs baseline: 1.5091x; 1.5091x over previous
#include <cuda_runtime.h>
#include <math.h>

#define Bn 32
#define N1 512
#define N2 512
#define Dd 128
#define Mw 256
#define Kd 96
#define BARRIERc 10000.0f

#define IG2 14.4269504088896f   /* log2(e)/gamma */
#define GLN2 0.069314718055995f /* gamma*ln(2)   */
#define INFf __int_as_float(0x7f800000)
#define FULLM 0xffffffffu

// dynamic smem layout (float offsets)
#define HSTRIDE 100
#define O_HA 0
#define O_HB (Mw * HSTRIDE)
#define O_LB (2 * Mw * HSTRIDE)
#define O_W  (O_LB + Mw)
#define O_TW (O_W + Mw)
#define O_FR (O_TW + Mw)
#define O_AF (O_FR + Kd)
#define O_AB (O_AF + Kd)
#define SMEM_FLOATS (O_AB + Kd)
#define SMEM_BYTES (SMEM_FLOATS * 4)

__device__ float g_T1[Bn], g_T2[Bn];
__device__ float g_node[Bn][Mw][Kd];

__device__ __forceinline__ float ex2a(float x) { float y; asm("ex2.approx.f32 %0, %1;" : "=f"(y) : "f"(x)); return y; }
__device__ __forceinline__ float lg2a(float x) { float y; asm("lg2.approx.f32 %0, %1;" : "=f"(y) : "f"(x)); return y; }
__device__ __forceinline__ float sqrta(float x) { float y; asm("sqrt.approx.f32 %0, %1;" : "=f"(y) : "f"(x)); return y; }

__device__ __forceinline__ unsigned f2o(float x) {
    unsigned u = __float_as_uint(x);
    return (u & 0x80000000u) ? ~u : (u | 0x80000000u);
}
__device__ __forceinline__ float o2f(unsigned v) {
    return __uint_as_float((v & 0x80000000u) ? (v ^ 0x80000000u) : ~v);
}

// ---------------- kernel 0 ----------------
__global__ void k0_maxes(const float* __restrict__ t1, const float* __restrict__ t2) {
    int b = blockIdx.x, t = threadIdx.x;
    float m1 = -3.4e38f, m2 = -3.4e38f;
    for (int i = t; i < N1; i += 256) m1 = fmaxf(m1, t1[b * N1 + i]);
    for (int i = t; i < N2; i += 256) m2 = fmaxf(m2, t2[b * N2 + i]);
    __shared__ float s1[8], s2[8];
    for (int o = 16; o; o >>= 1) {
        m1 = fmaxf(m1, __shfl_xor_sync(FULLM, m1, o));
        m2 = fmaxf(m2, __shfl_xor_sync(FULLM, m2, o));
    }
    if ((t & 31) == 0) { s1[t >> 5] = m1; s2[t >> 5] = m2; }
    __syncthreads();
    if (t == 0) {
        float a = s1[0], c = s2[0];
        for (int w = 1; w < 8; w++) { a = fmaxf(a, s1[w]); c = fmaxf(c, s2[w]); }
        g_T1[b] = a; g_T2[b] = c;
    }
}

// ---------------- kernel 2: node costs ----------------
__global__ void k2_node(const float* __restrict__ s1f, const float* __restrict__ s2f,
                        const float* __restrict__ glb_lb, const float* __restrict__ glb_ub,
                        const float* __restrict__ tw) {
    int b = blockIdx.y;
    int tid = threadIdx.x;
    int wq = tid >> 5, lane = tid & 31;
    int k = blockIdx.x * 8 + wq;
    __shared__ float s_lb[Mw], s_w[Mw], s_tw[Mw];
    __shared__ int   s_i0[32];
    __shared__ float s_w1[32];
    __shared__ float4 s_s1[32][32];
    float T2 = g_T2[b], T1 = g_T1[b];
    for (int i = tid; i < Mw; i += 256) {
        float lb = glb_lb[b * Mw + i] * T2;
        float ub = glb_ub[b * Mw + i] * T2;
        s_lb[i] = lb; s_w[i] = ub - lb; s_tw[i] = tw[b * Mw + i];
    }
    __syncthreads();
    float frk = (float)k / 95.0f;
    float invT2 = 1.f / T2, invT1 = 1.f / T1;
    const float* s2b = s2f + (size_t)b * N2 * Dd;
    const float* s1b = s1f + (size_t)b * N1 * Dd;
    int i0p = -1;
    float4 f0v = make_float4(0.f, 0.f, 0.f, 0.f), f1v = f0v;
    for (int mc = 0; mc < Mw; mc += 32) {
        __syncthreads();
        if (tid < 32) {
            float pos = s_tw[mc + tid] * invT1;
            float x = fminf(fmaxf(pos, 0.f), 1.f) * (float)(N1 - 1);
            int i0 = min(max((int)x, 0), N1 - 2);
            s_i0[tid] = i0;
            s_w1[tid] = x - (float)i0;
        }
        __syncthreads();
        for (int idx = tid; idx < 1024; idx += 256) {
            int ml = idx >> 5, l4 = idx & 31;
            const float4* r0 = (const float4*)(s1b + (size_t)s_i0[ml] * Dd);
            float4 f0 = r0[l4], f1 = r0[32 + l4];
            float ww = s_w1[ml];
            float4 o;
            o.x = f0.x + ww * (f1.x - f0.x);
            o.y = f0.y + ww * (f1.y - f0.y);
            o.z = f0.z + ww * (f1.z - f0.z);
            o.w = f0.w + ww * (f1.w - f0.w);
            s_s1[ml][l4] = o;
        }
        __syncthreads();
        for (int m0 = 0; m0 < 32; m0 += 4) {
            float acc[4], tks[4];
            #pragma unroll
            for (int u = 0; u < 4; u++) {
                int m = mc + m0 + u;
                float tk = s_lb[m] + s_w[m] * frk;
                tks[u] = tk;
                float x = fminf(fmaxf(tk * invT2, 0.f), 1.f) * (float)(N2 - 1);
                int i0 = min(max((int)x, 0), N2 - 2);
                float w = x - (float)i0;
                if (i0 != i0p) {
                    f0v = *((const float4*)(s2b + (size_t)i0 * Dd) + lane);
                    f1v = *((const float4*)(s2b + (size_t)(i0 + 1) * Dd) + lane);
                    i0p = i0;
                }
                float4 s1v = s_s1[m0 + u][lane];
                float d0 = s1v.x - (f0v.x + w * (f1v.x - f0v.x));
                float d1 = s1v.y - (f0v.y + w * (f1v.y - f0v.y));
                float d2 = s1v.z - (f0v.z + w * (f1v.z - f0v.z));
                float d3 = s1v.w - (f0v.w + w * (f1v.w - f0v.w));
                acc[u] = fmaf(d0, d0, fmaf(d1, d1, fmaf(d2, d2, d3 * d3)));
            }
            for (int o = 16; o; o >>= 1) {
                #pragma unroll
                for (int u = 0; u < 4; u++)
                    acc[u] += __shfl_xor_sync(FULLM, acc[u], o);
            }
            if (lane == 0) {
                #pragma unroll
                for (int u = 0; u < 4; u++) {
                    int m = mc + m0 + u;
                    float twm = s_tw[m];
                    float wt = 0.f;
                    if (m > 0) wt += twm - s_tw[m - 1];
                    if (m < Mw - 1) wt += s_tw[m + 1] - twm;
                    wt *= 0.5f;
                    float node = acc[u] * wt;
                    float tk = tks[u];
                    if (m == 0) node += BARRIERc * tk * tk;
                    if (m == Mw - 1) { float dd = tk - T2; node += BARRIERc * dd * dd; }
                    g_node[b][m][k] = node;
                }
            }
        }
    }
}

// ---------------- edge cost ----------------
__device__ __forceinline__ float edge_fn(float slope, float gub, float rwd) {
    float d1 = slope - 1.f;
    float n1 = fminf(slope, 0.f);
    float r2 = fmaxf(slope - gub, 0.f);
    float pen = fmaf(n1, n1, r2 * r2);
    return fmaf(BARRIERc, pen, rwd * d1 * d1);
}

// general windowed softmin (cold path)
__device__ __forceinline__ float softmin_win(
    const float* sa, const float* sfrac,
    int jlo, int jhi, float tref, float sgn, float invd,
    float lbp, float wp, float gub, float rwd) {
    float mval = INFf, ssum = 0.f;
    for (int j = jlo; j <= jhi; j++) {
        float tpj = lbp + wp * sfrac[j];
        float slope = sgn * (tref - tpj) * invd;
        float e = edge_fn(slope, gub, rwd);
        float xv = sa[j] + e;
        float dlt = xv - mval;
        float tt = ex2a(-fabsf(dlt) * IG2);
        if (dlt < 0.f) { ssum = fmaf(ssum, tt, 1.f); mval = xv; }
        else           { ssum += tt; }
    }
    return mval - GLN2 * lg2a(ssum);
}

// 2-candidate softmin (y may be INF)
__device__ __forceinline__ float sm2(float x, float y) {
    float mv = fminf(x, y);
    float ss = 1.f + ex2a(-fabsf(x - y) * IG2);
    return mv - GLN2 * lg2a(ss);
}

// ---------------- kernel 3: fused fwd+bwd scans + smem verify + output ----------------
__global__ void k3_fused(const float* __restrict__ tw, const float* __restrict__ reg_wt,
                         const float* __restrict__ lgu, const float* __restrict__ glb_lb,
                         const float* __restrict__ glb_ub, float* __restrict__ out) {
    extern __shared__ float sm[];
    float* histA = sm + O_HA;   // alpha_m rows, stride HSTRIDE
    float* histB = sm + O_HB;   // c_m = node_m + beta_m rows
    float* s_lb  = sm + O_LB;
    float* s_w   = sm + O_W;
    float* s_tw  = sm + O_TW;
    float* s_frac= sm + O_FR;
    float* s_aF  = sm + O_AF;
    float* s_aB  = sm + O_AB;

    int b = blockIdx.x;
    int tid = threadIdx.x;
    int wid = tid >> 5, lane = tid & 31;
    float T2 = g_T2[b];
    for (int i = tid; i < Mw; i += 256) {
        float lb = glb_lb[b * Mw + i] * T2;
        float ub = glb_ub[b * Mw + i] * T2;
        s_lb[i] = lb; s_w[i] = ub - lb; s_tw[i] = tw[b * Mw + i];
    }
    for (int i = tid; i < Kd; i += 256) s_frac[i] = (float)i / 95.0f;
    __syncthreads();

    float rw = reg_wt[b], gub = lgu[b];
    float gmin1 = fmaxf(1.f, gub);
    int kb = 3 * lane;
    bool gl = (lane >= 1), gr = (lane <= 30);

    if (wid == 0) {
        // ======== forward: value-only scan into histA ========
        {
            float a0 = g_node[b][0][kb], a1 = g_node[b][0][kb + 1], a2 = g_node[b][0][kb + 2];
            histA[kb] = a0; histA[kb + 1] = a1; histA[kb + 2] = a2;
            float nn0 = g_node[b][1][kb], nn1 = g_node[b][1][kb + 1], nn2 = g_node[b][1][kb + 2];
            int i2 = min(2, Mw - 1);
            float nf0 = g_node[b][i2][kb], nf1 = g_node[b][i2][kb + 1], nf2 = g_node[b][i2][kb + 2];
            float twp = s_tw[0];
            for (int i = 0; i < Mw - 1; i++) {
                float twn = s_tw[i + 1];
                float dtw = twn - twp;
                float invd = __fdividef(1.f, dtw);
                float rwd = rw * dtw;
                int ip = min(i + 3, Mw - 1);
                float nl0 = g_node[b][ip][kb], nl1 = g_node[b][ip][kb + 1], nl2 = g_node[b][ip][kb + 2];
                float sinv = s_w[i] * invd * (1.0f / 95.0f);
                float e2 = edge_fn(sinv, gub, rwd);
                float p2 = __shfl_up_sync(FULLM, a2, 1);
                float an0 = nn0 + sm2(a0 + rwd, gl ? p2 + e2 : INFf);
                float an1 = nn1 + sm2(a1 + rwd, a0 + e2);
                float an2 = nn2 + sm2(a2 + rwd, a1 + e2);
                float* hr = histA + (i + 1) * HSTRIDE;
                hr[kb] = an0; hr[kb + 1] = an1; hr[kb + 2] = an2;
                a0 = an0; a1 = an1; a2 = an2;
                nn0 = nf0; nn1 = nf1; nn2 = nf2;
                nf0 = nl0; nf1 = nl1; nf2 = nl2;
                twp = twn;
            }
        }
        // ======== verify: lane-parallel, smem-local min/max ========
        bool allok = (gub >= 0.f);
        for (int s = lane; s < Mw - 1; s += 32) {
            const float4* row = (const float4*)(histA + s * HSTRIDE);
            float mn = INFf, mx = -INFf;
            #pragma unroll
            for (int q = 0; q < Kd / 4; q++) {
                float4 v = row[q];
                mn = fminf(mn, fminf(fminf(v.x, v.y), fminf(v.z, v.w)));
                mx = fmaxf(mx, fmaxf(fmaxf(v.x, v.y), fmaxf(v.z, v.w)));
            }
            float dtw = s_tw[s + 1] - s_tw[s];
            float wp = s_w[s];
            float rwd = rw * dtw;
            float sinv = wp * __fdividef(1.f, dtw) * (1.0f / 95.0f);
            float thr = mx - mn + 15.f + rwd;
            bool ok = (s_lb[s + 1] == s_lb[s]) && (s_w[s + 1] == wp) && (wp > 0.f)
                   && (edge_fn(-sinv, gub, rwd) >= thr)
                   && (edge_fn(2.f * sinv, gub, rwd) >= thr)
                   && (2.f * sinv >= gmin1);
            allok = allok && ok;
        }
        // ======== cold general redo ========
        if (!__all_sync(FULLM, allok)) {
            float a0 = g_node[b][0][kb], a1 = g_node[b][0][kb + 1], a2 = g_node[b][0][kb + 2];
            histA[kb] = a0; histA[kb + 1] = a1; histA[kb + 2] = a2;
            float mina = o2f(__reduce_min_sync(FULLM, f2o(fminf(fminf(a0, a1), a2))));
            float maxa = o2f(__reduce_max_sync(FULLM, f2o(fmaxf(fmaxf(a0, a1), a2))));
            float lbp = s_lb[0], wp = s_w[0], twp = s_tw[0];
            float frs[3] = {(float)kb / 95.0f, (float)(kb + 1) / 95.0f, (float)(kb + 2) / 95.0f};
            for (int i = 0; i < Mw - 1; i++) {
                float lbn = s_lb[i + 1], wn = s_w[i + 1], twn = s_tw[i + 1];
                float dtw = twn - twp;
                float invd = __fdividef(1.f, dtw);
                float rwd = rw * dtw;
                s_aF[kb] = a0; s_aF[kb + 1] = a1; s_aF[kb + 2] = a2;
                __syncwarp();
                float marg = sqrta((maxa - mina + 16.f) * (1.f / BARRIERc));
                float inv95wp = __fdividef(95.0f, wp);
                bool degen = !(wp > 0.f);
                float loOff = (gub + marg) * dtw;
                float hiOff = marg * dtw;
                float res[3];
                #pragma unroll
                for (int r = 0; r < 3; r++) {
                    float tnk = lbn + wn * frs[r];
                    int jlo = max(0, __float2int_ru((tnk - loOff - lbp) * inv95wp));
                    int jhi = min(Kd - 1, __float2int_rd((tnk + hiOff - lbp) * inv95wp));
                    if (degen) { jlo = 0; jhi = Kd - 1; }
                    if (jhi < jlo) { int c = min(Kd - 1, max(0, jlo)); jlo = max(0, c - 1); jhi = min(Kd - 1, c + 1); }
                    res[r] = softmin_win(s_aF, s_frac, jlo, jhi, tnk, 1.f, invd, lbp, wp, gub, rwd);
                }
                __syncwarp();
                float an0 = g_node[b][i + 1][kb] + res[0];
                float an1 = g_node[b][i + 1][kb + 1] + res[1];
                float an2 = g_node[b][i + 1][kb + 2] + res[2];
                float* hr = histA + (i + 1) * HSTRIDE;
                hr[kb] = an0; hr[kb + 1] = an1; hr[kb + 2] = an2;
                mina = o2f(__reduce_min_sync(FULLM, f2o(fminf(fminf(an0, an1), an2))));
                maxa = o2f(__reduce_max_sync(FULLM, f2o(fmaxf(fmaxf(an0, an1), an2))));
                a0 = an0; a1 = an1; a2 = an2;
                lbp = lbn; wp = wn; twp = twn;
            }
        }
    } else if (wid == 1) {
        // ======== backward: value-only scan into histB (c = node + beta) ========
        {
            float a0 = g_node[b][Mw - 1][kb], a1 = g_node[b][Mw - 1][kb + 1], a2 = g_node[b][Mw - 1][kb + 2];
            float* hr = histB + (Mw - 1) * HSTRIDE;
            hr[kb] = a0; hr[kb + 1] = a1; hr[kb + 2] = a2;
            float ni0 = g_node[b][Mw - 2][kb], ni1 = g_node[b][Mw - 2][kb + 1], ni2 = g_node[b][Mw - 2][kb + 2];
            int i3 = max(Mw - 3, 0);
            float nf0 = g_node[b][i3][kb], nf1 = g_node[b][i3][kb + 1], nf2 = g_node[b][i3][kb + 2];
            float twp = s_tw[Mw - 1];
            for (int i = Mw - 2; i >= 0; i--) {
                float twj = s_tw[i];
                float dtw = twp - twj;
                float invd = __fdividef(1.f, dtw);
                float rwd = rw * dtw;
                int ip = max(i - 2, 0);
                float nl0 = g_node[b][ip][kb], nl1 = g_node[b][ip][kb + 1], nl2 = g_node[b][ip][kb + 2];
                float sinv = s_w[i + 1] * invd * (1.0f / 95.0f);
                float e2 = edge_fn(sinv, gub, rwd);
                float n0 = __shfl_down_sync(FULLM, a0, 1);
                float bn0 = sm2(a0 + rwd, a1 + e2);
                float bn1 = sm2(a1 + rwd, a2 + e2);
                float bn2 = sm2(a2 + rwd, gr ? n0 + e2 : INFf);
                float c0 = ni0 + bn0, c1 = ni1 + bn1, c2 = ni2 + bn2;
                float* hri = histB + i * HSTRIDE;
                hri[kb] = c0; hri[kb + 1] = c1; hri[kb + 2] = c2;
                a0 = c0; a1 = c1; a2 = c2;
                ni0 = nf0; ni1 = nf1; ni2 = nf2;
                nf0 = nl0; nf1 = nl1; nf2 = nl2;
                twp = twj;
            }
        }
        // ======== verify ========
        bool allok = (gub >= 0.f);
        for (int s = 1 + lane; s < Mw; s += 32) {
            const float4* row = (const float4*)(histB + s * HSTRIDE);
            float mn = INFf, mx = -INFf;
            #pragma unroll
            for (int q = 0; q < Kd / 4; q++) {
                float4 v = row[q];
                mn = fminf(mn, fminf(fminf(v.x, v.y), fminf(v.z, v.w)));
                mx = fmaxf(mx, fmaxf(fmaxf(v.x, v.y), fmaxf(v.z, v.w)));
            }
            float dtw = s_tw[s] - s_tw[s - 1];
            float wp = s_w[s];
            float rwd = rw * dtw;
            float sinv = wp * __fdividef(1.f, dtw) * (1.0f / 95.0f);
            float thr = mx - mn + 15.f + rwd;
            bool ok = (s_lb[s - 1] == s_lb[s]) && (s_w[s - 1] == wp) && (wp > 0.f)
                   && (edge_fn(-sinv, gub, rwd) >= thr)
                   && (edge_fn(2.f * sinv, gub, rwd) >= thr)
                   && (2.f * sinv >= gmin1);
            allok = allok && ok;
        }
        // ======== cold general redo ========
        if (!__all_sync(FULLM, allok)) {
            float a0 = g_node[b][Mw - 1][kb], a1 = g_node[b][Mw - 1][kb + 1], a2 = g_node[b][Mw - 1][kb + 2];
            float* hr = histB + (Mw - 1) * HSTRIDE;
            hr[kb] = a0; hr[kb + 1] = a1; hr[kb + 2] = a2;
            float mina = o2f(__reduce_min_sync(FULLM, f2o(fminf(fminf(a0, a1), a2))));
            float maxa = o2f(__reduce_max_sync(FULLM, f2o(fmaxf(fmaxf(a0, a1), a2))));
            float lbp = s_lb[Mw - 1], wp = s_w[Mw - 1], twp = s_tw[Mw - 1];
            float frs[3] = {(float)kb / 95.0f, (float)(kb + 1) / 95.0f, (float)(kb + 2) / 95.0f};
            for (int i = Mw - 2; i >= 0; i--) {
                float lbj = s_lb[i], wj = s_w[i], twj = s_tw[i];
                float dtw = twp - twj;
                float invd = __fdividef(1.f, dtw);
                float rwd = rw * dtw;
                s_aB[kb] = a0; s_aB[kb + 1] = a1; s_aB[kb + 2] = a2;
                __syncwarp();
                float marg = sqrta((maxa - mina + 16.f) * (1.f / BARRIERc));
                float inv95wp = __fdividef(95.0f, wp);
                bool degen = !(wp > 0.f);
                float loOff = marg * dtw;
                float hiOff = (gub + marg) * dtw;
                float res[3];
                #pragma unroll
                for (int r = 0; r < 3; r++) {
                    float tj = lbj + wj * frs[r];
                    int klo = max(0, __float2int_ru((tj - loOff - lbp) * inv95wp));
                    int khi = min(Kd - 1, __float2int_rd((tj + hiOff - lbp) * inv95wp));
                    if (degen) { klo = 0; khi = Kd - 1; }
                    if (khi < klo) { int cc = min(Kd - 1, max(0, klo)); klo = max(0, cc - 1); khi = min(Kd - 1, cc + 1); }
                    res[r] = softmin_win(s_aB, s_frac, klo, khi, tj, -1.f, invd, lbp, wp, gub, rwd);
                }
                __syncwarp();
                float c0 = g_node[b][i][kb] + res[0];
                float c1 = g_node[b][i][kb + 1] + res[1];
                float c2 = g_node[b][i][kb + 2] + res[2];
                float* hri = histB + i * HSTRIDE;
                hri[kb] = c0; hri[kb + 1] = c1; hri[kb + 2] = c2;
                mina = o2f(__reduce_min_sync(FULLM, f2o(fminf(fminf(c0, c1), c2))));
                maxa = o2f(__reduce_max_sync(FULLM, f2o(fmaxf(fmaxf(c0, c1), c2))));
                a0 = c0; a1 = c1; a2 = c2;
                lbp = lbj; wp = wj; twp = twj;
            }
        }
    }
    __syncthreads();

    // ======== output: 8 warps, v = alpha + c - node ========
    for (int m = wid; m < Mw; m += 8) {
        float lb = s_lb[m], w = s_w[m];
        const float* hA = histA + m * HSTRIDE;
        const float* hB = histB + m * HSTRIDE;
        float v[3], ta[3];
        #pragma unroll
        for (int r = 0; r < 3; r++) {
            int k = lane + 32 * r;
            v[r] = hA[k] + hB[k] - g_node[b][m][k];
            ta[r] = lb + w * ((float)k / 95.0f);
        }
        float l = fminf(fminf(v[0], v[1]), v[2]);
        float vmin = o2f(__reduce_min_sync(FULLM, f2o(l)));
        float ps = 0.f, pts = 0.f;
        #pragma unroll
        for (int r = 0; r < 3; r++) {
            float p = ex2a((vmin - v[r]) * IG2);
            ps += p;
            pts = fmaf(p, ta[r], pts);
        }
        for (int o = 16; o; o >>= 1) {
            ps += __shfl_xor_sync(FULLM, ps, o);
            pts += __shfl_xor_sync(FULLM, pts, o);
        }
        if (lane == 0) out[b * Mw + m] = pts / ps;
    }
}

extern "C" void kernel_launch(void* const* d_in, const int* in_sizes, int n_in,
                              void* d_out, int out_size) {
    const float* s1f    = (const float*)d_in[0];
    const float* s2f    = (const float*)d_in[1];
    const float* regw   = (const float*)d_in[2];
    const float* glb_lb = (const float*)d_in[3];
    const float* glb_ub = (const float*)d_in[4];
    const float* lgu    = (const float*)d_in[5];
    const float* t1     = (const float*)d_in[6];
    const float* t2     = (const float*)d_in[7];
    const float* twf    = (const float*)d_in[8];
    float* out = (float*)d_out;

    cudaFuncSetAttribute(k3_fused, cudaFuncAttributeMaxDynamicSharedMemorySize, SMEM_BYTES);

    k0_maxes<<<Bn, 256>>>(t1, t2);
    k2_node<<<dim3(Kd / 8, Bn), 256>>>(s1f, s2f, glb_lb, glb_ub, twf);
    k3_fused<<<Bn, 256, SMEM_BYTES>>>(twf, regw, lgu, glb_lb, glb_ub, out);
}

// round 10
// speedup vs baseline: 1.6641x; 1.1027x over previous
#include <cuda_runtime.h>
#include <math.h>

#define Bn 32
#define N1 512
#define N2 512
#define Dd 128
#define Mw 256
#define Kd 96
#define BARRIERc 10000.0f

#define IG2 14.4269504088896f   /* log2(e)/gamma */
#define GLN2 0.069314718055995f /* gamma*ln(2)   */
#define INFf __int_as_float(0x7f800000)
#define FULLM 0xffffffffu

// dynamic smem layout (float offsets) for k3
#define HSTRIDE 100
#define O_HA 0
#define O_HB (Mw * HSTRIDE)
#define O_LB (2 * Mw * HSTRIDE)
#define O_W  (O_LB + Mw)
#define O_TW (O_W + Mw)
#define O_FR (O_TW + Mw)
#define O_AF (O_FR + Kd)
#define O_AB (O_AF + Kd)
#define O_SC (O_AB + Kd)
#define SMEM_FLOATS (O_SC + 8)
#define SMEM_BYTES (SMEM_FLOATS * 4)

__device__ float g_node[Bn][Mw][Kd];

__device__ __forceinline__ float ex2a(float x) { float y; asm("ex2.approx.f32 %0, %1;" : "=f"(y) : "f"(x)); return y; }
__device__ __forceinline__ float lg2a(float x) { float y; asm("lg2.approx.f32 %0, %1;" : "=f"(y) : "f"(x)); return y; }
__device__ __forceinline__ float sqrta(float x) { float y; asm("sqrt.approx.f32 %0, %1;" : "=f"(y) : "f"(x)); return y; }

__device__ __forceinline__ unsigned f2o(float x) {
    unsigned u = __float_as_uint(x);
    return (u & 0x80000000u) ? ~u : (u | 0x80000000u);
}
__device__ __forceinline__ float o2f(unsigned v) {
    return __uint_as_float((v & 0x80000000u) ? (v ^ 0x80000000u) : ~v);
}

// block-wide max of p[0..n), 256 threads; scratch = 8 floats smem
__device__ __forceinline__ float block_max(const float* __restrict__ p, int n, float* scratch) {
    int tid = threadIdx.x;
    float m = -3.4e38f;
    for (int i = tid; i < n; i += 256) m = fmaxf(m, p[i]);
    for (int o = 16; o; o >>= 1) m = fmaxf(m, __shfl_xor_sync(FULLM, m, o));
    if ((tid & 31) == 0) scratch[tid >> 5] = m;
    __syncthreads();
    float r = scratch[0];
    #pragma unroll
    for (int w = 1; w < 8; w++) r = fmaxf(r, scratch[w]);
    return r;
}

// ---------------- kernel 2: node costs (fused maxes + s1 interp + smem staging) ----------------
__global__ void k2_node(const float* __restrict__ s1f, const float* __restrict__ s2f,
                        const float* __restrict__ glb_lb, const float* __restrict__ glb_ub,
                        const float* __restrict__ tw, const float* __restrict__ t1g,
                        const float* __restrict__ t2g) {
    int b = blockIdx.y;
    int tid = threadIdx.x;
    int wq = tid >> 5, lane = tid & 31;
    int k = blockIdx.x * 8 + wq;
    __shared__ float s_lb[Mw], s_w[Mw], s_tw[Mw];
    __shared__ int   s_i0[32];
    __shared__ float s_w1[32];
    __shared__ float4 s_s1[32][32];
    __shared__ float sc1[8], sc2[8];
    float T1 = block_max(t1g + b * N1, N1, sc1);
    __syncthreads();
    float T2 = block_max(t2g + b * N2, N2, sc2);
    for (int i = tid; i < Mw; i += 256) {
        float lb = glb_lb[b * Mw + i] * T2;
        float ub = glb_ub[b * Mw + i] * T2;
        s_lb[i] = lb; s_w[i] = ub - lb; s_tw[i] = tw[b * Mw + i];
    }
    __syncthreads();
    float frk = (float)k / 95.0f;
    float invT2 = 1.f / T2, invT1 = 1.f / T1;
    const float* s2b = s2f + (size_t)b * N2 * Dd;
    const float* s1b = s1f + (size_t)b * N1 * Dd;
    int i0p = -1;
    float4 f0v = make_float4(0.f, 0.f, 0.f, 0.f), f1v = f0v;
    for (int mc = 0; mc < Mw; mc += 32) {
        __syncthreads();
        if (tid < 32) {
            float pos = s_tw[mc + tid] * invT1;
            float x = fminf(fmaxf(pos, 0.f), 1.f) * (float)(N1 - 1);
            int i0 = min(max((int)x, 0), N1 - 2);
            s_i0[tid] = i0;
            s_w1[tid] = x - (float)i0;
        }
        __syncthreads();
        for (int idx = tid; idx < 1024; idx += 256) {
            int ml = idx >> 5, l4 = idx & 31;
            const float4* r0 = (const float4*)(s1b + (size_t)s_i0[ml] * Dd);
            float4 f0 = r0[l4], f1 = r0[32 + l4];
            float ww = s_w1[ml];
            float4 o;
            o.x = f0.x + ww * (f1.x - f0.x);
            o.y = f0.y + ww * (f1.y - f0.y);
            o.z = f0.z + ww * (f1.z - f0.z);
            o.w = f0.w + ww * (f1.w - f0.w);
            s_s1[ml][l4] = o;
        }
        __syncthreads();
        for (int m0 = 0; m0 < 32; m0 += 4) {
            float acc[4], tks[4];
            #pragma unroll
            for (int u = 0; u < 4; u++) {
                int m = mc + m0 + u;
                float tk = s_lb[m] + s_w[m] * frk;
                tks[u] = tk;
                float x = fminf(fmaxf(tk * invT2, 0.f), 1.f) * (float)(N2 - 1);
                int i0 = min(max((int)x, 0), N2 - 2);
                float w = x - (float)i0;
                if (i0 != i0p) {
                    f0v = *((const float4*)(s2b + (size_t)i0 * Dd) + lane);
                    f1v = *((const float4*)(s2b + (size_t)(i0 + 1) * Dd) + lane);
                    i0p = i0;
                }
                float4 s1v = s_s1[m0 + u][lane];
                float d0 = s1v.x - (f0v.x + w * (f1v.x - f0v.x));
                float d1 = s1v.y - (f0v.y + w * (f1v.y - f0v.y));
                float d2 = s1v.z - (f0v.z + w * (f1v.z - f0v.z));
                float d3 = s1v.w - (f0v.w + w * (f1v.w - f0v.w));
                acc[u] = fmaf(d0, d0, fmaf(d1, d1, fmaf(d2, d2, d3 * d3)));
            }
            for (int o = 16; o; o >>= 1) {
                #pragma unroll
                for (int u = 0; u < 4; u++)
                    acc[u] += __shfl_xor_sync(FULLM, acc[u], o);
            }
            if (lane == 0) {
                #pragma unroll
                for (int u = 0; u < 4; u++) {
                    int m = mc + m0 + u;
                    float twm = s_tw[m];
                    float wt = 0.f;
                    if (m > 0) wt += twm - s_tw[m - 1];
                    if (m < Mw - 1) wt += s_tw[m + 1] - twm;
                    wt *= 0.5f;
                    float node = acc[u] * wt;
                    float tk = tks[u];
                    if (m == 0) node += BARRIERc * tk * tk;
                    if (m == Mw - 1) { float dd = tk - T2; node += BARRIERc * dd * dd; }
                    g_node[b][m][k] = node;
                }
            }
        }
    }
}

// ---------------- edge cost ----------------
__device__ __forceinline__ float edge_fn(float slope, float gub, float rwd) {
    float d1 = slope - 1.f;
    float n1 = fminf(slope, 0.f);
    float r2 = fmaxf(slope - gub, 0.f);
    float pen = fmaf(n1, n1, r2 * r2);
    return fmaf(BARRIERc, pen, rwd * d1 * d1);
}

// general windowed softmin (cold path)
__device__ __forceinline__ float softmin_win(
    const float* sa, const float* sfrac,
    int jlo, int jhi, float tref, float sgn, float invd,
    float lbp, float wp, float gub, float rwd) {
    float mval = INFf, ssum = 0.f;
    for (int j = jlo; j <= jhi; j++) {
        float tpj = lbp + wp * sfrac[j];
        float slope = sgn * (tref - tpj) * invd;
        float e = edge_fn(slope, gub, rwd);
        float xv = sa[j] + e;
        float dlt = xv - mval;
        float tt = ex2a(-fabsf(dlt) * IG2);
        if (dlt < 0.f) { ssum = fmaf(ssum, tt, 1.f); mval = xv; }
        else           { ssum += tt; }
    }
    return mval - GLN2 * lg2a(ssum);
}

// 2-candidate softmin (y may be INF)
__device__ __forceinline__ float sm2(float x, float y) {
    float mv = fminf(x, y);
    float ss = 1.f + ex2a(-fabsf(x - y) * IG2);
    return mv - GLN2 * lg2a(ss);
}

// fwd step body: uses prefetch regs NN* (node[i+1]), then reloads them with node[i+4]
#define FWD_BODY(i, NN0, NN1, NN2)                                        \
{                                                                          \
    float twn = s_tw[(i) + 1];                                             \
    float dtw = twn - twp;                                                 \
    float invd = __fdividef(1.f, dtw);                                     \
    float rwd = rw * dtw;                                                  \
    float sinv = s_w[i] * invd * (1.0f / 95.0f);                           \
    float e2 = edge_fn(sinv, gub, rwd);                                    \
    float p2 = __shfl_up_sync(FULLM, a2, 1);                               \
    float an0 = NN0 + sm2(a0 + rwd, gl ? p2 + e2 : INFf);                  \
    float an1 = NN1 + sm2(a1 + rwd, a0 + e2);                              \
    float an2 = NN2 + sm2(a2 + rwd, a1 + e2);                              \
    float* hr = histA + ((i) + 1) * HSTRIDE;                               \
    hr[kb] = an0; hr[kb + 1] = an1; hr[kb + 2] = an2;                      \
    a0 = an0; a1 = an1; a2 = an2;                                          \
    const float* np = &g_node[b][min((i) + 4, Mw - 1)][kb];                \
    NN0 = np[0]; NN1 = np[1]; NN2 = np[2];                                 \
    twp = twn;                                                             \
}

// bwd step body: uses prefetch regs NI* (node[i]), then reloads with node[i-3]
#define BWD_BODY(i, NI0, NI1, NI2)                                         \
{                                                                          \
    float twj = s_tw[i];                                                   \
    float dtw = twp - twj;                                                 \
    float invd = __fdividef(1.f, dtw);                                     \
    float rwd = rw * dtw;                                                  \
    float sinv = s_w[(i) + 1] * invd * (1.0f / 95.0f);                     \
    float e2 = edge_fn(sinv, gub, rwd);                                    \
    float n0 = __shfl_down_sync(FULLM, a0, 1);                             \
    float bn0 = sm2(a0 + rwd, a1 + e2);                                    \
    float bn1 = sm2(a1 + rwd, a2 + e2);                                    \
    float bn2 = sm2(a2 + rwd, gr ? n0 + e2 : INFf);                        \
    float c0 = NI0 + bn0, c1 = NI1 + bn1, c2 = NI2 + bn2;                  \
    float* hri = histB + (i) * HSTRIDE;                                    \
    hri[kb] = c0; hri[kb + 1] = c1; hri[kb + 2] = c2;                      \
    a0 = c0; a1 = c1; a2 = c2;                                             \
    const float* np = &g_node[b][max((i) - 3, 0)][kb];                     \
    NI0 = np[0]; NI1 = np[1]; NI2 = np[2];                                 \
    twp = twj;                                                             \
}

// ---------------- kernel 3: fused fwd+bwd scans + smem verify + output ----------------
__global__ void k3_fused(const float* __restrict__ tw, const float* __restrict__ reg_wt,
                         const float* __restrict__ lgu, const float* __restrict__ glb_lb,
                         const float* __restrict__ glb_ub, const float* __restrict__ t2g,
                         float* __restrict__ out) {
    extern __shared__ float sm[];
    float* histA = sm + O_HA;
    float* histB = sm + O_HB;
    float* s_lb  = sm + O_LB;
    float* s_w   = sm + O_W;
    float* s_tw  = sm + O_TW;
    float* s_frac= sm + O_FR;
    float* s_aF  = sm + O_AF;
    float* s_aB  = sm + O_AB;
    float* s_sc  = sm + O_SC;

    int b = blockIdx.x;
    int tid = threadIdx.x;
    int wid = tid >> 5, lane = tid & 31;
    float T2 = block_max(t2g + b * N2, N2, s_sc);
    for (int i = tid; i < Mw; i += 256) {
        float lb = glb_lb[b * Mw + i] * T2;
        float ub = glb_ub[b * Mw + i] * T2;
        s_lb[i] = lb; s_w[i] = ub - lb; s_tw[i] = tw[b * Mw + i];
    }
    for (int i = tid; i < Kd; i += 256) s_frac[i] = (float)i / 95.0f;
    __syncthreads();

    float rw = reg_wt[b], gub = lgu[b];
    float gmin1 = fmaxf(1.f, gub);
    int kb = 3 * lane;
    bool gl = (lane >= 1), gr = (lane <= 30);

    if (wid == 0) {
        // ======== forward: software-pipelined value-only scan ========
        {
            float a0 = g_node[b][0][kb], a1 = g_node[b][0][kb + 1], a2 = g_node[b][0][kb + 2];
            histA[kb] = a0; histA[kb + 1] = a1; histA[kb + 2] = a2;
            float pA0 = g_node[b][1][kb], pA1 = g_node[b][1][kb + 1], pA2 = g_node[b][1][kb + 2];
            float pB0 = g_node[b][2][kb], pB1 = g_node[b][2][kb + 1], pB2 = g_node[b][2][kb + 2];
            float pC0 = g_node[b][3][kb], pC1 = g_node[b][3][kb + 1], pC2 = g_node[b][3][kb + 2];
            float twp = s_tw[0];
            for (int g = 0; g < 85; g++) {
                int i = 3 * g;
                FWD_BODY(i,     pA0, pA1, pA2);
                FWD_BODY(i + 1, pB0, pB1, pB2);
                FWD_BODY(i + 2, pC0, pC1, pC2);
            }
        }
        __syncwarp();
        // ======== verify: lane-parallel, smem-local ========
        bool allok = (gub >= 0.f);
        for (int s = lane; s < Mw - 1; s += 32) {
            const float4* row = (const float4*)(histA + s * HSTRIDE);
            float mn = INFf, mx = -INFf;
            #pragma unroll
            for (int q = 0; q < Kd / 4; q++) {
                float4 v = row[q];
                mn = fminf(mn, fminf(fminf(v.x, v.y), fminf(v.z, v.w)));
                mx = fmaxf(mx, fmaxf(fmaxf(v.x, v.y), fmaxf(v.z, v.w)));
            }
            float dtw = s_tw[s + 1] - s_tw[s];
            float wp = s_w[s];
            float rwd = rw * dtw;
            float sinv = wp * __fdividef(1.f, dtw) * (1.0f / 95.0f);
            float thr = mx - mn + 15.f + rwd;
            bool ok = (s_lb[s + 1] == s_lb[s]) && (s_w[s + 1] == wp) && (wp > 0.f)
                   && (edge_fn(-sinv, gub, rwd) >= thr)
                   && (edge_fn(2.f * sinv, gub, rwd) >= thr)
                   && (2.f * sinv >= gmin1);
            allok = allok && ok;
        }
        // ======== cold general redo ========
        if (!__all_sync(FULLM, allok)) {
            float a0 = g_node[b][0][kb], a1 = g_node[b][0][kb + 1], a2 = g_node[b][0][kb + 2];
            histA[kb] = a0; histA[kb + 1] = a1; histA[kb + 2] = a2;
            float mina = o2f(__reduce_min_sync(FULLM, f2o(fminf(fminf(a0, a1), a2))));
            float maxa = o2f(__reduce_max_sync(FULLM, f2o(fmaxf(fmaxf(a0, a1), a2))));
            float lbp = s_lb[0], wp = s_w[0], twp = s_tw[0];
            float frs[3] = {(float)kb / 95.0f, (float)(kb + 1) / 95.0f, (float)(kb + 2) / 95.0f};
            for (int i = 0; i < Mw - 1; i++) {
                float lbn = s_lb[i + 1], wn = s_w[i + 1], twn = s_tw[i + 1];
                float dtw = twn - twp;
                float invd = __fdividef(1.f, dtw);
                float rwd = rw * dtw;
                s_aF[kb] = a0; s_aF[kb + 1] = a1; s_aF[kb + 2] = a2;
                __syncwarp();
                float marg = sqrta((maxa - mina + 16.f) * (1.f / BARRIERc));
                float inv95wp = __fdividef(95.0f, wp);
                bool degen = !(wp > 0.f);
                float loOff = (gub + marg) * dtw;
                float hiOff = marg * dtw;
                float res[3];
                #pragma unroll
                for (int r = 0; r < 3; r++) {
                    float tnk = lbn + wn * frs[r];
                    int jlo = max(0, __float2int_ru((tnk - loOff - lbp) * inv95wp));
                    int jhi = min(Kd - 1, __float2int_rd((tnk + hiOff - lbp) * inv95wp));
                    if (degen) { jlo = 0; jhi = Kd - 1; }
                    if (jhi < jlo) { int c = min(Kd - 1, max(0, jlo)); jlo = max(0, c - 1); jhi = min(Kd - 1, c + 1); }
                    res[r] = softmin_win(s_aF, s_frac, jlo, jhi, tnk, 1.f, invd, lbp, wp, gub, rwd);
                }
                __syncwarp();
                float an0 = g_node[b][i + 1][kb] + res[0];
                float an1 = g_node[b][i + 1][kb + 1] + res[1];
                float an2 = g_node[b][i + 1][kb + 2] + res[2];
                float* hr = histA + (i + 1) * HSTRIDE;
                hr[kb] = an0; hr[kb + 1] = an1; hr[kb + 2] = an2;
                mina = o2f(__reduce_min_sync(FULLM, f2o(fminf(fminf(an0, an1), an2))));
                maxa = o2f(__reduce_max_sync(FULLM, f2o(fmaxf(fmaxf(an0, an1), an2))));
                a0 = an0; a1 = an1; a2 = an2;
                lbp = lbn; wp = wn; twp = twn;
            }
        }
    } else if (wid == 1) {
        // ======== backward: software-pipelined value-only scan ========
        {
            float a0 = g_node[b][Mw - 1][kb], a1 = g_node[b][Mw - 1][kb + 1], a2 = g_node[b][Mw - 1][kb + 2];
            float* hr = histB + (Mw - 1) * HSTRIDE;
            hr[kb] = a0; hr[kb + 1] = a1; hr[kb + 2] = a2;
            float pA0 = g_node[b][Mw - 2][kb], pA1 = g_node[b][Mw - 2][kb + 1], pA2 = g_node[b][Mw - 2][kb + 2];
            float pB0 = g_node[b][Mw - 3][kb], pB1 = g_node[b][Mw - 3][kb + 1], pB2 = g_node[b][Mw - 3][kb + 2];
            float pC0 = g_node[b][Mw - 4][kb], pC1 = g_node[b][Mw - 4][kb + 1], pC2 = g_node[b][Mw - 4][kb + 2];
            float twp = s_tw[Mw - 1];
            for (int g = 0; g < 85; g++) {
                int i = Mw - 2 - 3 * g;
                BWD_BODY(i,     pA0, pA1, pA2);
                BWD_BODY(i - 1, pB0, pB1, pB2);
                BWD_BODY(i - 2, pC0, pC1, pC2);
            }
        }
        __syncwarp();
        // ======== verify ========
        bool allok = (gub >= 0.f);
        for (int s = 1 + lane; s < Mw; s += 32) {
            const float4* row = (const float4*)(histB + s * HSTRIDE);
            float mn = INFf, mx = -INFf;
            #pragma unroll
            for (int q = 0; q < Kd / 4; q++) {
                float4 v = row[q];
                mn = fminf(mn, fminf(fminf(v.x, v.y), fminf(v.z, v.w)));
                mx = fmaxf(mx, fmaxf(fmaxf(v.x, v.y), fmaxf(v.z, v.w)));
            }
            float dtw = s_tw[s] - s_tw[s - 1];
            float wp = s_w[s];
            float rwd = rw * dtw;
            float sinv = wp * __fdividef(1.f, dtw) * (1.0f / 95.0f);
            float thr = mx - mn + 15.f + rwd;
            bool ok = (s_lb[s - 1] == s_lb[s]) && (s_w[s - 1] == wp) && (wp > 0.f)
                   && (edge_fn(-sinv, gub, rwd) >= thr)
                   && (edge_fn(2.f * sinv, gub, rwd) >= thr)
                   && (2.f * sinv >= gmin1);
            allok = allok && ok;
        }
        // ======== cold general redo ========
        if (!__all_sync(FULLM, allok)) {
            float a0 = g_node[b][Mw - 1][kb], a1 = g_node[b][Mw - 1][kb + 1], a2 = g_node[b][Mw - 1][kb + 2];
            float* hr = histB + (Mw - 1) * HSTRIDE;
            hr[kb] = a0; hr[kb + 1] = a1; hr[kb + 2] = a2;
            float mina = o2f(__reduce_min_sync(FULLM, f2o(fminf(fminf(a0, a1), a2))));
            float maxa = o2f(__reduce_max_sync(FULLM, f2o(fmaxf(fmaxf(a0, a1), a2))));
            float lbp = s_lb[Mw - 1], wp = s_w[Mw - 1], twp = s_tw[Mw - 1];
            float frs[3] = {(float)kb / 95.0f, (float)(kb + 1) / 95.0f, (float)(kb + 2) / 95.0f};
            for (int i = Mw - 2; i >= 0; i--) {
                float lbj = s_lb[i], wj = s_w[i], twj = s_tw[i];
                float dtw = twp - twj;
                float invd = __fdividef(1.f, dtw);
                float rwd = rw * dtw;
                s_aB[kb] = a0; s_aB[kb + 1] = a1; s_aB[kb + 2] = a2;
                __syncwarp();
                float marg = sqrta((maxa - mina + 16.f) * (1.f / BARRIERc));
                float inv95wp = __fdividef(95.0f, wp);
                bool degen = !(wp > 0.f);
                float loOff = marg * dtw;
                float hiOff = (gub + marg) * dtw;
                float res[3];
                #pragma unroll
                for (int r = 0; r < 3; r++) {
                    float tj = lbj + wj * frs[r];
                    int klo = max(0, __float2int_ru((tj - loOff - lbp) * inv95wp));
                    int khi = min(Kd - 1, __float2int_rd((tj + hiOff - lbp) * inv95wp));
                    if (degen) { klo = 0; khi = Kd - 1; }
                    if (khi < klo) { int cc = min(Kd - 1, max(0, klo)); klo = max(0, cc - 1); khi = min(Kd - 1, cc + 1); }
                    res[r] = softmin_win(s_aB, s_frac, klo, khi, tj, -1.f, invd, lbp, wp, gub, rwd);
                }
                __syncwarp();
                float c0 = g_node[b][i][kb] + res[0];
                float c1 = g_node[b][i][kb + 1] + res[1];
                float c2 = g_node[b][i][kb + 2] + res[2];
                float* hri = histB + i * HSTRIDE;
                hri[kb] = c0; hri[kb + 1] = c1; hri[kb + 2] = c2;
                mina = o2f(__reduce_min_sync(FULLM, f2o(fminf(fminf(c0, c1), c2))));
                maxa = o2f(__reduce_max_sync(FULLM, f2o(fmaxf(fmaxf(c0, c1), c2))));
                a0 = c0; a1 = c1; a2 = c2;
                lbp = lbj; wp = wj; twp = twj;
            }
        }
    }
    __syncthreads();

    // ======== output: 8 warps, v = alpha + c - node ========
    for (int m = wid; m < Mw; m += 8) {
        float lb = s_lb[m], w = s_w[m];
        const float* hA = histA + m * HSTRIDE;
        const float* hB = histB + m * HSTRIDE;
        float v[3], ta[3];
        #pragma unroll
        for (int r = 0; r < 3; r++) {
            int k = lane + 32 * r;
            v[r] = hA[k] + hB[k] - g_node[b][m][k];
            ta[r] = lb + w * ((float)k / 95.0f);
        }
        float l = fminf(fminf(v[0], v[1]), v[2]);
        float vmin = o2f(__reduce_min_sync(FULLM, f2o(l)));
        float ps = 0.f, pts = 0.f;
        #pragma unroll
        for (int r = 0; r < 3; r++) {
            float p = ex2a((vmin - v[r]) * IG2);
            ps += p;
            pts = fmaf(p, ta[r], pts);
        }
        for (int o = 16; o; o >>= 1) {
            ps += __shfl_xor_sync(FULLM, ps, o);
            pts += __shfl_xor_sync(FULLM, pts, o);
        }
        if (lane == 0) out[b * Mw + m] = pts / ps;
    }
}

extern "C" void kernel_launch(void* const* d_in, const int* in_sizes, int n_in,
                              void* d_out, int out_size) {
    const float* s1f    = (const float*)d_in[0];
    const float* s2f    = (const float*)d_in[1];
    const float* regw   = (const float*)d_in[2];
    const float* glb_lb = (const float*)d_in[3];
    const float* glb_ub = (const float*)d_in[4];
    const float* lgu    = (const float*)d_in[5];
    const float* t1     = (const float*)d_in[6];
    const float* t2     = (const float*)d_in[7];
    const float* twf    = (const float*)d_in[8];
    float* out = (float*)d_out;

    cudaFuncSetAttribute(k3_fused, cudaFuncAttributeMaxDynamicSharedMemorySize, SMEM_BYTES);

    k2_node<<<dim3(Kd / 8, Bn), 256>>>(s1f, s2f, glb_lb, glb_ub, twf, t1, t2);
    k3_fused<<<Bn, 256, SMEM_BYTES>>>(twf, regw, lgu, glb_lb, glb_ub, t2, out);
}

// round 11
// speedup vs baseline: 1.9174x; 1.1522x over previous
#include <cuda_runtime.h>
#include <math.h>

#define Bn 32
#define N1 512
#define N2 512
#define Dd 128
#define Mw 256
#define Kd 96
#define BARRIERc 10000.0f

#define IG2 14.4269504088896f   /* log2(e)/gamma */
#define GLN2 0.069314718055995f /* gamma*ln(2)   */
#define INFf __int_as_float(0x7f800000)
#define NINFf __int_as_float(0xff800000)
#define FULLM 0xffffffffu

// dynamic smem layout (float offsets) for k3
#define HSTRIDE 100
#define O_HA 0
#define O_HB (Mw * HSTRIDE)
#define O_LB (2 * Mw * HSTRIDE)
#define O_W   (O_LB + Mw)
#define O_TW  (O_W + Mw)
#define O_FR  (O_TW + Mw)
#define O_AF  (O_FR + Kd)
#define O_AB  (O_AF + Kd)
#define O_SC  (O_AB + Kd)
#define O_RWD (O_SC + 8)
#define O_E2F (O_RWD + Mw)
#define O_E2B (O_E2F + Mw)
#define O_CPF (O_E2B + Mw)
#define O_CPB (O_CPF + Mw)
#define SMEM_FLOATS (O_CPB + Mw)
#define SMEM_BYTES (SMEM_FLOATS * 4)

__device__ float g_node[Bn][Mw][Kd];

__device__ __forceinline__ float ex2a(float x) { float y; asm("ex2.approx.f32 %0, %1;" : "=f"(y) : "f"(x)); return y; }
__device__ __forceinline__ float lg2a(float x) { float y; asm("lg2.approx.f32 %0, %1;" : "=f"(y) : "f"(x)); return y; }
__device__ __forceinline__ float sqrta(float x) { float y; asm("sqrt.approx.f32 %0, %1;" : "=f"(y) : "f"(x)); return y; }

__device__ __forceinline__ unsigned f2o(float x) {
    unsigned u = __float_as_uint(x);
    return (u & 0x80000000u) ? ~u : (u | 0x80000000u);
}
__device__ __forceinline__ float o2f(unsigned v) {
    return __uint_as_float((v & 0x80000000u) ? (v ^ 0x80000000u) : ~v);
}

// block-wide max of p[0..n), 256 threads; scratch = 8 floats smem
__device__ __forceinline__ float block_max(const float* __restrict__ p, int n, float* scratch) {
    int tid = threadIdx.x;
    float m = -3.4e38f;
    for (int i = tid; i < n; i += 256) m = fmaxf(m, p[i]);
    for (int o = 16; o; o >>= 1) m = fmaxf(m, __shfl_xor_sync(FULLM, m, o));
    if ((tid & 31) == 0) scratch[tid >> 5] = m;
    __syncthreads();
    float r = scratch[0];
    #pragma unroll
    for (int w = 1; w < 8; w++) r = fmaxf(r, scratch[w]);
    return r;
}

// ---------------- kernel 2: node costs (one 32-m chunk per block) ----------------
__global__ void k2_node(const float* __restrict__ s1f, const float* __restrict__ s2f,
                        const float* __restrict__ glb_lb, const float* __restrict__ glb_ub,
                        const float* __restrict__ tw, const float* __restrict__ t1g,
                        const float* __restrict__ t2g) {
    int b = blockIdx.z;
    int mc = blockIdx.y * 32;
    int tid = threadIdx.x;
    int wq = tid >> 5, lane = tid & 31;
    int k = blockIdx.x * 8 + wq;
    __shared__ float s_lb[Mw], s_w[Mw], s_tw[Mw];
    __shared__ int   s_i0[32];
    __shared__ float s_w1[32];
    __shared__ float4 s_s1[32][32];
    __shared__ float sc1[8], sc2[8];
    float T1 = block_max(t1g + b * N1, N1, sc1);
    __syncthreads();
    float T2 = block_max(t2g + b * N2, N2, sc2);
    for (int i = tid; i < Mw; i += 256) {
        float lb = glb_lb[b * Mw + i] * T2;
        float ub = glb_ub[b * Mw + i] * T2;
        s_lb[i] = lb; s_w[i] = ub - lb; s_tw[i] = tw[b * Mw + i];
    }
    __syncthreads();
    float frk = (float)k / 95.0f;
    float invT2 = 1.f / T2, invT1 = 1.f / T1;
    const float* s2b = s2f + (size_t)b * N2 * Dd;
    const float* s1b = s1f + (size_t)b * N1 * Dd;
    int i0p = -1;
    float4 f0v = make_float4(0.f, 0.f, 0.f, 0.f), f1v = f0v;

    if (tid < 32) {
        float pos = s_tw[mc + tid] * invT1;
        float x = fminf(fmaxf(pos, 0.f), 1.f) * (float)(N1 - 1);
        int i0 = min(max((int)x, 0), N1 - 2);
        s_i0[tid] = i0;
        s_w1[tid] = x - (float)i0;
    }
    __syncthreads();
    for (int idx = tid; idx < 1024; idx += 256) {
        int ml = idx >> 5, l4 = idx & 31;
        const float4* r0 = (const float4*)(s1b + (size_t)s_i0[ml] * Dd);
        float4 f0 = r0[l4], f1 = r0[32 + l4];
        float ww = s_w1[ml];
        float4 o;
        o.x = f0.x + ww * (f1.x - f0.x);
        o.y = f0.y + ww * (f1.y - f0.y);
        o.z = f0.z + ww * (f1.z - f0.z);
        o.w = f0.w + ww * (f1.w - f0.w);
        s_s1[ml][l4] = o;
    }
    __syncthreads();
    for (int m0 = 0; m0 < 32; m0 += 4) {
        float acc[4], tks[4];
        #pragma unroll
        for (int u = 0; u < 4; u++) {
            int m = mc + m0 + u;
            float tk = s_lb[m] + s_w[m] * frk;
            tks[u] = tk;
            float x = fminf(fmaxf(tk * invT2, 0.f), 1.f) * (float)(N2 - 1);
            int i0 = min(max((int)x, 0), N2 - 2);
            float w = x - (float)i0;
            if (i0 != i0p) {
                f0v = *((const float4*)(s2b + (size_t)i0 * Dd) + lane);
                f1v = *((const float4*)(s2b + (size_t)(i0 + 1) * Dd) + lane);
                i0p = i0;
            }
            float4 s1v = s_s1[m0 + u][lane];
            float d0 = s1v.x - (f0v.x + w * (f1v.x - f0v.x));
            float d1 = s1v.y - (f0v.y + w * (f1v.y - f0v.y));
            float d2 = s1v.z - (f0v.z + w * (f1v.z - f0v.z));
            float d3 = s1v.w - (f0v.w + w * (f1v.w - f0v.w));
            acc[u] = fmaf(d0, d0, fmaf(d1, d1, fmaf(d2, d2, d3 * d3)));
        }
        for (int o = 16; o; o >>= 1) {
            #pragma unroll
            for (int u = 0; u < 4; u++)
                acc[u] += __shfl_xor_sync(FULLM, acc[u], o);
        }
        if (lane == 0) {
            #pragma unroll
            for (int u = 0; u < 4; u++) {
                int m = mc + m0 + u;
                float twm = s_tw[m];
                float wt = 0.f;
                if (m > 0) wt += twm - s_tw[m - 1];
                if (m < Mw - 1) wt += s_tw[m + 1] - twm;
                wt *= 0.5f;
                float node = acc[u] * wt;
                float tk = tks[u];
                if (m == 0) node += BARRIERc * tk * tk;
                if (m == Mw - 1) { float dd = tk - T2; node += BARRIERc * dd * dd; }
                g_node[b][m][k] = node;
            }
        }
    }
}

// ---------------- edge cost ----------------
__device__ __forceinline__ float edge_fn(float slope, float gub, float rwd) {
    float d1 = slope - 1.f;
    float n1 = fminf(slope, 0.f);
    float r2 = fmaxf(slope - gub, 0.f);
    float pen = fmaf(n1, n1, r2 * r2);
    return fmaf(BARRIERc, pen, rwd * d1 * d1);
}

// general windowed softmin (cold path)
__device__ __forceinline__ float softmin_win(
    const float* sa, const float* sfrac,
    int jlo, int jhi, float tref, float sgn, float invd,
    float lbp, float wp, float gub, float rwd) {
    float mval = INFf, ssum = 0.f;
    for (int j = jlo; j <= jhi; j++) {
        float tpj = lbp + wp * sfrac[j];
        float slope = sgn * (tref - tpj) * invd;
        float e = edge_fn(slope, gub, rwd);
        float xv = sa[j] + e;
        float dlt = xv - mval;
        float tt = ex2a(-fabsf(dlt) * IG2);
        if (dlt < 0.f) { ssum = fmaf(ssum, tt, 1.f); mval = xv; }
        else           { ssum += tt; }
    }
    return mval - GLN2 * lg2a(ssum);
}

// 2-candidate softmin (y may be INF)
__device__ __forceinline__ float sm2(float x, float y) {
    float mv = fminf(x, y);
    float ss = 1.f + ex2a(-fabsf(x - y) * IG2);
    return mv - GLN2 * lg2a(ss);
}

// fwd step: tables give rwd/e2; NN* = node[i+1]; reload from running pointer
#define FWD_BODY(i, NN0, NN1, NN2)                                         \
{                                                                          \
    float rwd = s_rwd[i];                                                  \
    float e2  = s_e2f[i];                                                  \
    float p2 = __shfl_up_sync(FULLM, a2, 1);                               \
    float an0 = NN0 + sm2(a0 + rwd, gl ? p2 + e2 : INFf);                  \
    float an1 = NN1 + sm2(a1 + rwd, a0 + e2);                              \
    float an2 = NN2 + sm2(a2 + rwd, a1 + e2);                              \
    float* hr = histA + ((i) + 1) * HSTRIDE;                               \
    hr[kb] = an0; hr[kb + 1] = an1; hr[kb + 2] = an2;                      \
    a0 = an0; a1 = an1; a2 = an2;                                          \
    NN0 = npF[0]; NN1 = npF[1]; NN2 = npF[2]; npF += Kd;                   \
}
#define FWD_TAIL(i, NN0, NN1, NN2)                                         \
{                                                                          \
    float rwd = s_rwd[i];                                                  \
    float e2  = s_e2f[i];                                                  \
    float p2 = __shfl_up_sync(FULLM, a2, 1);                               \
    float an0 = NN0 + sm2(a0 + rwd, gl ? p2 + e2 : INFf);                  \
    float an1 = NN1 + sm2(a1 + rwd, a0 + e2);                              \
    float an2 = NN2 + sm2(a2 + rwd, a1 + e2);                              \
    float* hr = histA + ((i) + 1) * HSTRIDE;                               \
    hr[kb] = an0; hr[kb + 1] = an1; hr[kb + 2] = an2;                      \
    a0 = an0; a1 = an1; a2 = an2;                                          \
}

// bwd step: NI* = node[i]; reload from running pointer (descending)
#define BWD_BODY(i, NI0, NI1, NI2)                                         \
{                                                                          \
    float rwd = s_rwd[i];                                                  \
    float e2  = s_e2b[i];                                                  \
    float n0 = __shfl_down_sync(FULLM, a0, 1);                             \
    float bn0 = sm2(a0 + rwd, a1 + e2);                                    \
    float bn1 = sm2(a1 + rwd, a2 + e2);                                    \
    float bn2 = sm2(a2 + rwd, gr ? n0 + e2 : INFf);                        \
    float c0 = NI0 + bn0, c1 = NI1 + bn1, c2 = NI2 + bn2;                  \
    float* hri = histB + (i) * HSTRIDE;                                    \
    hri[kb] = c0; hri[kb + 1] = c1; hri[kb + 2] = c2;                      \
    a0 = c0; a1 = c1; a2 = c2;                                             \
    NI0 = npB[0]; NI1 = npB[1]; NI2 = npB[2]; npB -= Kd;                   \
}
#define BWD_TAIL(i, NI0, NI1, NI2)                                         \
{                                                                          \
    float rwd = s_rwd[i];                                                  \
    float e2  = s_e2b[i];                                                  \
    float n0 = __shfl_down_sync(FULLM, a0, 1);                             \
    float bn0 = sm2(a0 + rwd, a1 + e2);                                    \
    float bn1 = sm2(a1 + rwd, a2 + e2);                                    \
    float bn2 = sm2(a2 + rwd, gr ? n0 + e2 : INFf);                        \
    float c0 = NI0 + bn0, c1 = NI1 + bn1, c2 = NI2 + bn2;                  \
    float* hri = histB + (i) * HSTRIDE;                                    \
    hri[kb] = c0; hri[kb + 1] = c1; hri[kb + 2] = c2;                      \
    a0 = c0; a1 = c1; a2 = c2;                                             \
}

// ---------------- kernel 3: fused scans + precomputed step tables ----------------
__global__ void k3_fused(const float* __restrict__ tw, const float* __restrict__ reg_wt,
                         const float* __restrict__ lgu, const float* __restrict__ glb_lb,
                         const float* __restrict__ glb_ub, const float* __restrict__ t2g,
                         float* __restrict__ out) {
    extern __shared__ float sm[];
    float* histA = sm + O_HA;
    float* histB = sm + O_HB;
    float* s_lb  = sm + O_LB;
    float* s_w   = sm + O_W;
    float* s_tw  = sm + O_TW;
    float* s_frac= sm + O_FR;
    float* s_aF  = sm + O_AF;
    float* s_aB  = sm + O_AB;
    float* s_sc  = sm + O_SC;
    float* s_rwd = sm + O_RWD;
    float* s_e2f = sm + O_E2F;
    float* s_e2b = sm + O_E2B;
    float* s_cpf = sm + O_CPF;
    float* s_cpb = sm + O_CPB;

    int b = blockIdx.x;
    int tid = threadIdx.x;
    int wid = tid >> 5, lane = tid & 31;
    float T2 = block_max(t2g + b * N2, N2, s_sc);
    float rw = reg_wt[b], gub = lgu[b];
    float gmin1 = fmaxf(1.f, gub);
    for (int i = tid; i < Mw; i += 256) {
        float lb = glb_lb[b * Mw + i] * T2;
        float ub = glb_ub[b * Mw + i] * T2;
        s_lb[i] = lb; s_w[i] = ub - lb; s_tw[i] = tw[b * Mw + i];
    }
    for (int i = tid; i < Kd; i += 256) s_frac[i] = (float)i / 95.0f;
    __syncthreads();
    // ---- per-step tables (one pass: 255 < 256 threads) ----
    if (tid < Mw - 1) {
        int i = tid;
        float dtw = s_tw[i + 1] - s_tw[i];
        float invd = __fdividef(1.f, dtw);
        float rwd = rw * dtw;
        s_rwd[i] = rwd;
        bool unif = (s_lb[i + 1] == s_lb[i]) && (s_w[i + 1] == s_w[i]) && (gub >= 0.f);
        // fwd uses prev-grid width s_w[i]
        {
            float wp = s_w[i];
            float sinv = wp * invd * (1.0f / 95.0f);
            s_e2f[i] = edge_fn(sinv, gub, rwd);
            bool ok = unif && (wp > 0.f) && (2.f * sinv >= gmin1);
            float emin = fminf(edge_fn(-sinv, gub, rwd), edge_fn(2.f * sinv, gub, rwd));
            s_cpf[i] = ok ? (emin - 15.f - rwd) : NINFf;
        }
        // bwd uses next-grid width s_w[i+1]
        {
            float wp = s_w[i + 1];
            float sinv = wp * invd * (1.0f / 95.0f);
            s_e2b[i] = edge_fn(sinv, gub, rwd);
            bool ok = unif && (wp > 0.f) && (2.f * sinv >= gmin1);
            float emin = fminf(edge_fn(-sinv, gub, rwd), edge_fn(2.f * sinv, gub, rwd));
            s_cpb[i] = ok ? (emin - 15.f - rwd) : NINFf;
        }
    }
    __syncthreads();

    int kb = 3 * lane;
    bool gl = (lane >= 1), gr = (lane <= 30);

    if (wid == 0) {
        // ======== forward scan (table-driven, prefetched) ========
        {
            float a0 = g_node[b][0][kb], a1 = g_node[b][0][kb + 1], a2 = g_node[b][0][kb + 2];
            histA[kb] = a0; histA[kb + 1] = a1; histA[kb + 2] = a2;
            float pA0 = g_node[b][1][kb], pA1 = g_node[b][1][kb + 1], pA2 = g_node[b][1][kb + 2];
            float pB0 = g_node[b][2][kb], pB1 = g_node[b][2][kb + 1], pB2 = g_node[b][2][kb + 2];
            float pC0 = g_node[b][3][kb], pC1 = g_node[b][3][kb + 1], pC2 = g_node[b][3][kb + 2];
            const float* npF = &g_node[b][4][kb];
            for (int g = 0; g < 84; g++) {
                int i = 3 * g;
                FWD_BODY(i,     pA0, pA1, pA2);
                FWD_BODY(i + 1, pB0, pB1, pB2);
                FWD_BODY(i + 2, pC0, pC1, pC2);
            }
            FWD_TAIL(252, pA0, pA1, pA2);
            FWD_TAIL(253, pB0, pB1, pB2);
            FWD_TAIL(254, pC0, pC1, pC2);
        }
        __syncwarp();
        // ======== verify vs precomputed caps ========
        bool allok = true;
        for (int s = lane; s < Mw - 1; s += 32) {
            const float4* row = (const float4*)(histA + s * HSTRIDE);
            float mn = INFf, mx = -INFf;
            #pragma unroll
            for (int q = 0; q < Kd / 4; q++) {
                float4 v = row[q];
                mn = fminf(mn, fminf(fminf(v.x, v.y), fminf(v.z, v.w)));
                mx = fmaxf(mx, fmaxf(fmaxf(v.x, v.y), fmaxf(v.z, v.w)));
            }
            allok = allok && ((mx - mn) <= s_cpf[s]);
        }
        // ======== cold general redo ========
        if (!__all_sync(FULLM, allok)) {
            float a0 = g_node[b][0][kb], a1 = g_node[b][0][kb + 1], a2 = g_node[b][0][kb + 2];
            histA[kb] = a0; histA[kb + 1] = a1; histA[kb + 2] = a2;
            float mina = o2f(__reduce_min_sync(FULLM, f2o(fminf(fminf(a0, a1), a2))));
            float maxa = o2f(__reduce_max_sync(FULLM, f2o(fmaxf(fmaxf(a0, a1), a2))));
            float lbp = s_lb[0], wp = s_w[0], twp = s_tw[0];
            float frs[3] = {(float)kb / 95.0f, (float)(kb + 1) / 95.0f, (float)(kb + 2) / 95.0f};
            for (int i = 0; i < Mw - 1; i++) {
                float lbn = s_lb[i + 1], wn = s_w[i + 1], twn = s_tw[i + 1];
                float dtw = twn - twp;
                float invd = __fdividef(1.f, dtw);
                float rwd = rw * dtw;
                s_aF[kb] = a0; s_aF[kb + 1] = a1; s_aF[kb + 2] = a2;
                __syncwarp();
                float marg = sqrta((maxa - mina + 16.f) * (1.f / BARRIERc));
                float inv95wp = __fdividef(95.0f, wp);
                bool degen = !(wp > 0.f);
                float loOff = (gub + marg) * dtw;
                float hiOff = marg * dtw;
                float res[3];
                #pragma unroll
                for (int r = 0; r < 3; r++) {
                    float tnk = lbn + wn * frs[r];
                    int jlo = max(0, __float2int_ru((tnk - loOff - lbp) * inv95wp));
                    int jhi = min(Kd - 1, __float2int_rd((tnk + hiOff - lbp) * inv95wp));
                    if (degen) { jlo = 0; jhi = Kd - 1; }
                    if (jhi < jlo) { int c = min(Kd - 1, max(0, jlo)); jlo = max(0, c - 1); jhi = min(Kd - 1, c + 1); }
                    res[r] = softmin_win(s_aF, s_frac, jlo, jhi, tnk, 1.f, invd, lbp, wp, gub, rwd);
                }
                __syncwarp();
                float an0 = g_node[b][i + 1][kb] + res[0];
                float an1 = g_node[b][i + 1][kb + 1] + res[1];
                float an2 = g_node[b][i + 1][kb + 2] + res[2];
                float* hr = histA + (i + 1) * HSTRIDE;
                hr[kb] = an0; hr[kb + 1] = an1; hr[kb + 2] = an2;
                mina = o2f(__reduce_min_sync(FULLM, f2o(fminf(fminf(an0, an1), an2))));
                maxa = o2f(__reduce_max_sync(FULLM, f2o(fmaxf(fmaxf(an0, an1), an2))));
                a0 = an0; a1 = an1; a2 = an2;
                lbp = lbn; wp = wn; twp = twn;
            }
        }
    } else if (wid == 1) {
        // ======== backward scan ========
        {
            float a0 = g_node[b][Mw - 1][kb], a1 = g_node[b][Mw - 1][kb + 1], a2 = g_node[b][Mw - 1][kb + 2];
            float* hr = histB + (Mw - 1) * HSTRIDE;
            hr[kb] = a0; hr[kb + 1] = a1; hr[kb + 2] = a2;
            float pA0 = g_node[b][Mw - 2][kb], pA1 = g_node[b][Mw - 2][kb + 1], pA2 = g_node[b][Mw - 2][kb + 2];
            float pB0 = g_node[b][Mw - 3][kb], pB1 = g_node[b][Mw - 3][kb + 1], pB2 = g_node[b][Mw - 3][kb + 2];
            float pC0 = g_node[b][Mw - 4][kb], pC1 = g_node[b][Mw - 4][kb + 1], pC2 = g_node[b][Mw - 4][kb + 2];
            const float* npB = &g_node[b][Mw - 5][kb];
            for (int g = 0; g < 84; g++) {
                int i = Mw - 2 - 3 * g;
                BWD_BODY(i,     pA0, pA1, pA2);
                BWD_BODY(i - 1, pB0, pB1, pB2);
                BWD_BODY(i - 2, pC0, pC1, pC2);
            }
            BWD_TAIL(2, pA0, pA1, pA2);
            BWD_TAIL(1, pB0, pB1, pB2);
            BWD_TAIL(0, pC0, pC1, pC2);
        }
        __syncwarp();
        // ======== verify ========
        bool allok = true;
        for (int s = 1 + lane; s < Mw; s += 32) {
            const float4* row = (const float4*)(histB + s * HSTRIDE);
            float mn = INFf, mx = -INFf;
            #pragma unroll
            for (int q = 0; q < Kd / 4; q++) {
                float4 v = row[q];
                mn = fminf(mn, fminf(fminf(v.x, v.y), fminf(v.z, v.w)));
                mx = fmaxf(mx, fmaxf(fmaxf(v.x, v.y), fmaxf(v.z, v.w)));
            }
            allok = allok && ((mx - mn) <= s_cpb[s - 1]);
        }
        // ======== cold general redo ========
        if (!__all_sync(FULLM, allok)) {
            float a0 = g_node[b][Mw - 1][kb], a1 = g_node[b][Mw - 1][kb + 1], a2 = g_node[b][Mw - 1][kb + 2];
            float* hr = histB + (Mw - 1) * HSTRIDE;
            hr[kb] = a0; hr[kb + 1] = a1; hr[kb + 2] = a2;
            float mina = o2f(__reduce_min_sync(FULLM, f2o(fminf(fminf(a0, a1), a2))));
            float maxa = o2f(__reduce_max_sync(FULLM, f2o(fmaxf(fmaxf(a0, a1), a2))));
            float lbp = s_lb[Mw - 1], wp = s_w[Mw - 1], twp = s_tw[Mw - 1];
            float frs[3] = {(float)kb / 95.0f, (float)(kb + 1) / 95.0f, (float)(kb + 2) / 95.0f};
            for (int i = Mw - 2; i >= 0; i--) {
                float lbj = s_lb[i], wj = s_w[i], twj = s_tw[i];
                float dtw = twp - twj;
                float invd = __fdividef(1.f, dtw);
                float rwd = rw * dtw;
                s_aB[kb] = a0; s_aB[kb + 1] = a1; s_aB[kb + 2] = a2;
                __syncwarp();
                float marg = sqrta((maxa - mina + 16.f) * (1.f / BARRIERc));
                float inv95wp = __fdividef(95.0f, wp);
                bool degen = !(wp > 0.f);
                float loOff = marg * dtw;
                float hiOff = (gub + marg) * dtw;
                float res[3];
                #pragma unroll
                for (int r = 0; r < 3; r++) {
                    float tj = lbj + wj * frs[r];
                    int klo = max(0, __float2int_ru((tj - loOff - lbp) * inv95wp));
                    int khi = min(Kd - 1, __float2int_rd((tj + hiOff - lbp) * inv95wp));
                    if (degen) { klo = 0; khi = Kd - 1; }
                    if (khi < klo) { int cc = min(Kd - 1, max(0, klo)); klo = max(0, cc - 1); khi = min(Kd - 1, cc + 1); }
                    res[r] = softmin_win(s_aB, s_frac, klo, khi, tj, -1.f, invd, lbp, wp, gub, rwd);
                }
                __syncwarp();
                float c0 = g_node[b][i][kb] + res[0];
                float c1 = g_node[b][i][kb + 1] + res[1];
                float c2 = g_node[b][i][kb + 2] + res[2];
                float* hri = histB + i * HSTRIDE;
                hri[kb] = c0; hri[kb + 1] = c1; hri[kb + 2] = c2;
                mina = o2f(__reduce_min_sync(FULLM, f2o(fminf(fminf(c0, c1), c2))));
                maxa = o2f(__reduce_max_sync(FULLM, f2o(fmaxf(fmaxf(c0, c1), c2))));
                a0 = c0; a1 = c1; a2 = c2;
                lbp = lbj; wp = wj; twp = twj;
            }
        }
    }
    __syncthreads();

    // ======== output: 8 warps, v = alpha + c - node ========
    for (int m = wid; m < Mw; m += 8) {
        float lb = s_lb[m], w = s_w[m];
        const float* hA = histA + m * HSTRIDE;
        const float* hB = histB + m * HSTRIDE;
        float v[3], ta[3];
        #pragma unroll
        for (int r = 0; r < 3; r++) {
            int k = lane + 32 * r;
            v[r] = hA[k] + hB[k] - g_node[b][m][k];
            ta[r] = lb + w * ((float)k / 95.0f);
        }
        float l = fminf(fminf(v[0], v[1]), v[2]);
        float vmin = o2f(__reduce_min_sync(FULLM, f2o(l)));
        float ps = 0.f, pts = 0.f;
        #pragma unroll
        for (int r = 0; r < 3; r++) {
            float p = ex2a((vmin - v[r]) * IG2);
            ps += p;
            pts = fmaf(p, ta[r], pts);
        }
        for (int o = 16; o; o >>= 1) {
            ps += __shfl_xor_sync(FULLM, ps, o);
            pts += __shfl_xor_sync(FULLM, pts, o);
        }
        if (lane == 0) out[b * Mw + m] = pts / ps;
    }
}

extern "C" void kernel_launch(void* const* d_in, const int* in_sizes, int n_in,
                              void* d_out, int out_size) {
    const float* s1f    = (const float*)d_in[0];
    const float* s2f    = (const float*)d_in[1];
    const float* regw   = (const float*)d_in[2];
    const float* glb_lb = (const float*)d_in[3];
    const float* glb_ub = (const float*)d_in[4];
    const float* lgu    = (const float*)d_in[5];
    const float* t1     = (const float*)d_in[6];
    const float* t2     = (const float*)d_in[7];
    const float* twf    = (const float*)d_in[8];
    float* out = (float*)d_out;

    cudaFuncSetAttribute(k3_fused, cudaFuncAttributeMaxDynamicSharedMemorySize, SMEM_BYTES);

    k2_node<<<dim3(Kd / 8, 8, Bn), 256>>>(s1f, s2f, glb_lb, glb_ub, twf, t1, t2);
    k3_fused<<<Bn, 256, SMEM_BYTES>>>(twf, regw, lgu, glb_lb, glb_ub, t2, out);
}

// round 12
// speedup vs baseline: 1.9197x; 1.0012x over previous
#include <cuda_runtime.h>
#include <math.h>

#define Bn 32
#define N1 512
#define N2 512
#define Dd 128
#define Mw 256
#define Kd 96
#define BARRIERc 10000.0f

#define IG2 14.4269504088896f   /* log2(e)/gamma */
#define GLN2 0.069314718055995f /* gamma*ln(2)   */
#define INFf __int_as_float(0x7f800000)
#define NINFf __int_as_float(0xff800000)
#define FULLM 0xffffffffu

// dynamic smem layout (float offsets) for k3
#define HSTRIDE 100
#define O_HA 0
#define O_HB (Mw * HSTRIDE)
#define O_LB (2 * Mw * HSTRIDE)
#define O_W   (O_LB + Mw)
#define O_TW  (O_W + Mw)
#define O_FR  (O_TW + Mw)
#define O_AF  (O_FR + Kd)
#define O_AB  (O_AF + Kd)
#define O_RWD (O_AB + Kd)
#define O_E2F (O_RWD + Mw)
#define O_E2B (O_E2F + Mw)
#define O_CPF (O_E2B + Mw)
#define O_CPB (O_CPF + Mw)
#define SMEM_FLOATS (O_CPB + Mw)
#define SMEM_BYTES (SMEM_FLOATS * 4)

__device__ float g_T1[Bn], g_T2[Bn];
__device__ float g_node[Bn][Mw][Kd];

__device__ __forceinline__ float ex2a(float x) { float y; asm("ex2.approx.f32 %0, %1;" : "=f"(y) : "f"(x)); return y; }
__device__ __forceinline__ float lg2a(float x) { float y; asm("lg2.approx.f32 %0, %1;" : "=f"(y) : "f"(x)); return y; }
__device__ __forceinline__ float sqrta(float x) { float y; asm("sqrt.approx.f32 %0, %1;" : "=f"(y) : "f"(x)); return y; }

__device__ __forceinline__ unsigned f2o(float x) {
    unsigned u = __float_as_uint(x);
    return (u & 0x80000000u) ? ~u : (u | 0x80000000u);
}
__device__ __forceinline__ float o2f(unsigned v) {
    return __uint_as_float((v & 0x80000000u) ? (v ^ 0x80000000u) : ~v);
}

// ---------------- kernel 0: per-batch maxima ----------------
__global__ void k0_maxes(const float* __restrict__ t1, const float* __restrict__ t2) {
    int b = blockIdx.x, t = threadIdx.x;
    float m1 = -3.4e38f, m2 = -3.4e38f;
    for (int i = t; i < N1; i += 256) m1 = fmaxf(m1, t1[b * N1 + i]);
    for (int i = t; i < N2; i += 256) m2 = fmaxf(m2, t2[b * N2 + i]);
    __shared__ float s1[8], s2[8];
    for (int o = 16; o; o >>= 1) {
        m1 = fmaxf(m1, __shfl_xor_sync(FULLM, m1, o));
        m2 = fmaxf(m2, __shfl_xor_sync(FULLM, m2, o));
    }
    if ((t & 31) == 0) { s1[t >> 5] = m1; s2[t >> 5] = m2; }
    __syncthreads();
    if (t == 0) {
        float a = s1[0], c = s2[0];
        for (int w = 1; w < 8; w++) { a = fmaxf(a, s1[w]); c = fmaxf(c, s2[w]); }
        g_T1[b] = a; g_T2[b] = c;
    }
}

// ---------------- kernel 2: node costs (one 32-m chunk per block) ----------------
__global__ void k2_node(const float* __restrict__ s1f, const float* __restrict__ s2f,
                        const float* __restrict__ glb_lb, const float* __restrict__ glb_ub,
                        const float* __restrict__ tw) {
    int b = blockIdx.z;
    int mc = blockIdx.y * 32;
    int tid = threadIdx.x;
    int wq = tid >> 5, lane = tid & 31;
    int k = blockIdx.x * 8 + wq;
    __shared__ float s_lb[Mw], s_w[Mw], s_tw[Mw];
    __shared__ int   s_i0[32];
    __shared__ float s_w1[32];
    __shared__ float4 s_s1[32][32];
    float T1 = g_T1[b], T2 = g_T2[b];
    for (int i = tid; i < Mw; i += 256) {
        float lb = glb_lb[b * Mw + i] * T2;
        float ub = glb_ub[b * Mw + i] * T2;
        s_lb[i] = lb; s_w[i] = ub - lb; s_tw[i] = tw[b * Mw + i];
    }
    __syncthreads();
    float frk = (float)k / 95.0f;
    float invT2 = 1.f / T2, invT1 = 1.f / T1;
    const float* s2b = s2f + (size_t)b * N2 * Dd;
    const float* s1b = s1f + (size_t)b * N1 * Dd;
    int i0p = -1;
    float4 f0v = make_float4(0.f, 0.f, 0.f, 0.f), f1v = f0v;

    if (tid < 32) {
        float pos = s_tw[mc + tid] * invT1;
        float x = fminf(fmaxf(pos, 0.f), 1.f) * (float)(N1 - 1);
        int i0 = min(max((int)x, 0), N1 - 2);
        s_i0[tid] = i0;
        s_w1[tid] = x - (float)i0;
    }
    __syncthreads();
    for (int idx = tid; idx < 1024; idx += 256) {
        int ml = idx >> 5, l4 = idx & 31;
        const float4* r0 = (const float4*)(s1b + (size_t)s_i0[ml] * Dd);
        float4 f0 = r0[l4], f1 = r0[32 + l4];
        float ww = s_w1[ml];
        float4 o;
        o.x = f0.x + ww * (f1.x - f0.x);
        o.y = f0.y + ww * (f1.y - f0.y);
        o.z = f0.z + ww * (f1.z - f0.z);
        o.w = f0.w + ww * (f1.w - f0.w);
        s_s1[ml][l4] = o;
    }
    __syncthreads();
    for (int m0 = 0; m0 < 32; m0 += 4) {
        float acc[4], tks[4];
        #pragma unroll
        for (int u = 0; u < 4; u++) {
            int m = mc + m0 + u;
            float tk = s_lb[m] + s_w[m] * frk;
            tks[u] = tk;
            float x = fminf(fmaxf(tk * invT2, 0.f), 1.f) * (float)(N2 - 1);
            int i0 = min(max((int)x, 0), N2 - 2);
            float w = x - (float)i0;
            if (i0 != i0p) {
                f0v = *((const float4*)(s2b + (size_t)i0 * Dd) + lane);
                f1v = *((const float4*)(s2b + (size_t)(i0 + 1) * Dd) + lane);
                i0p = i0;
            }
            float4 s1v = s_s1[m0 + u][lane];
            float d0 = s1v.x - (f0v.x + w * (f1v.x - f0v.x));
            float d1 = s1v.y - (f0v.y + w * (f1v.y - f0v.y));
            float d2 = s1v.z - (f0v.z + w * (f1v.z - f0v.z));
            float d3 = s1v.w - (f0v.w + w * (f1v.w - f0v.w));
            acc[u] = fmaf(d0, d0, fmaf(d1, d1, fmaf(d2, d2, d3 * d3)));
        }
        for (int o = 16; o; o >>= 1) {
            #pragma unroll
            for (int u = 0; u < 4; u++)
                acc[u] += __shfl_xor_sync(FULLM, acc[u], o);
        }
        if (lane == 0) {
            #pragma unroll
            for (int u = 0; u < 4; u++) {
                int m = mc + m0 + u;
                float twm = s_tw[m];
                float wt = 0.f;
                if (m > 0) wt += twm - s_tw[m - 1];
                if (m < Mw - 1) wt += s_tw[m + 1] - twm;
                wt *= 0.5f;
                float node = acc[u] * wt;
                float tk = tks[u];
                if (m == 0) node += BARRIERc * tk * tk;
                if (m == Mw - 1) { float dd = tk - T2; node += BARRIERc * dd * dd; }
                g_node[b][m][k] = node;
            }
        }
    }
}

// ---------------- edge cost ----------------
__device__ __forceinline__ float edge_fn(float slope, float gub, float rwd) {
    float d1 = slope - 1.f;
    float n1 = fminf(slope, 0.f);
    float r2 = fmaxf(slope - gub, 0.f);
    float pen = fmaf(n1, n1, r2 * r2);
    return fmaf(BARRIERc, pen, rwd * d1 * d1);
}

// general windowed softmin (cold path)
__device__ __forceinline__ float softmin_win(
    const float* sa, const float* sfrac,
    int jlo, int jhi, float tref, float sgn, float invd,
    float lbp, float wp, float gub, float rwd) {
    float mval = INFf, ssum = 0.f;
    for (int j = jlo; j <= jhi; j++) {
        float tpj = lbp + wp * sfrac[j];
        float slope = sgn * (tref - tpj) * invd;
        float e = edge_fn(slope, gub, rwd);
        float xv = sa[j] + e;
        float dlt = xv - mval;
        float tt = ex2a(-fabsf(dlt) * IG2);
        if (dlt < 0.f) { ssum = fmaf(ssum, tt, 1.f); mval = xv; }
        else           { ssum += tt; }
    }
    return mval - GLN2 * lg2a(ssum);
}

// 2-candidate softmin (y may be INF), fused final fma
__device__ __forceinline__ float sm2(float x, float y) {
    float mv = fminf(x, y);
    float ss = 1.f + ex2a(-fabsf(x - y) * IG2);
    return fmaf(-GLN2, lg2a(ss), mv);
}

// fwd step: table values in registers (RWD/E2); prefetch next set after use
#define FWD_BODY(i, NN0, NN1, NN2, RWD, E2)                                \
{                                                                          \
    float p2 = __shfl_up_sync(FULLM, a2, 1);                               \
    float an0 = NN0 + sm2(a0 + RWD, gl ? p2 + E2 : INFf);                  \
    float an1 = NN1 + sm2(a1 + RWD, a0 + E2);                              \
    float an2 = NN2 + sm2(a2 + RWD, a1 + E2);                              \
    float* hr = histA + ((i) + 1) * HSTRIDE;                               \
    hr[kb] = an0; hr[kb + 1] = an1; hr[kb + 2] = an2;                      \
    a0 = an0; a1 = an1; a2 = an2;                                          \
    NN0 = npF[0]; NN1 = npF[1]; NN2 = npF[2]; npF += Kd;                   \
    int tnx = min((i) + 3, Mw - 2);                                        \
    RWD = s_rwd[tnx]; E2 = s_e2f[tnx];                                     \
}
#define FWD_TAIL(i, NN0, NN1, NN2, RWD, E2)                                \
{                                                                          \
    float p2 = __shfl_up_sync(FULLM, a2, 1);                               \
    float an0 = NN0 + sm2(a0 + RWD, gl ? p2 + E2 : INFf);                  \
    float an1 = NN1 + sm2(a1 + RWD, a0 + E2);                              \
    float an2 = NN2 + sm2(a2 + RWD, a1 + E2);                              \
    float* hr = histA + ((i) + 1) * HSTRIDE;                               \
    hr[kb] = an0; hr[kb + 1] = an1; hr[kb + 2] = an2;                      \
    a0 = an0; a1 = an1; a2 = an2;                                          \
}

// bwd step
#define BWD_BODY(i, NI0, NI1, NI2, RWD, E2)                                \
{                                                                          \
    float n0 = __shfl_down_sync(FULLM, a0, 1);                             \
    float bn0 = sm2(a0 + RWD, a1 + E2);                                    \
    float bn1 = sm2(a1 + RWD, a2 + E2);                                    \
    float bn2 = sm2(a2 + RWD, gr ? n0 + E2 : INFf);                        \
    float c0 = NI0 + bn0, c1 = NI1 + bn1, c2 = NI2 + bn2;                  \
    float* hri = histB + (i) * HSTRIDE;                                    \
    hri[kb] = c0; hri[kb + 1] = c1; hri[kb + 2] = c2;                      \
    a0 = c0; a1 = c1; a2 = c2;                                             \
    NI0 = npB[0]; NI1 = npB[1]; NI2 = npB[2]; npB -= Kd;                   \
    int tnx = max((i) - 3, 0);                                             \
    RWD = s_rwd[tnx]; E2 = s_e2b[tnx];                                     \
}
#define BWD_TAIL(i, NI0, NI1, NI2, RWD, E2)                                \
{                                                                          \
    float n0 = __shfl_down_sync(FULLM, a0, 1);                             \
    float bn0 = sm2(a0 + RWD, a1 + E2);                                    \
    float bn1 = sm2(a1 + RWD, a2 + E2);                                    \
    float bn2 = sm2(a2 + RWD, gr ? n0 + E2 : INFf);                        \
    float c0 = NI0 + bn0, c1 = NI1 + bn1, c2 = NI2 + bn2;                  \
    float* hri = histB + (i) * HSTRIDE;                                    \
    hri[kb] = c0; hri[kb + 1] = c1; hri[kb + 2] = c2;                      \
    a0 = c0; a1 = c1; a2 = c2;                                             \
}

// ---------------- kernel 3: fused scans, register-prefetched tables ----------------
__global__ void k3_fused(const float* __restrict__ tw, const float* __restrict__ reg_wt,
                         const float* __restrict__ lgu, const float* __restrict__ glb_lb,
                         const float* __restrict__ glb_ub, float* __restrict__ out) {
    extern __shared__ float sm[];
    float* histA = sm + O_HA;
    float* histB = sm + O_HB;
    float* s_lb  = sm + O_LB;
    float* s_w   = sm + O_W;
    float* s_tw  = sm + O_TW;
    float* s_frac= sm + O_FR;
    float* s_aF  = sm + O_AF;
    float* s_aB  = sm + O_AB;
    float* s_rwd = sm + O_RWD;
    float* s_e2f = sm + O_E2F;
    float* s_e2b = sm + O_E2B;
    float* s_cpf = sm + O_CPF;
    float* s_cpb = sm + O_CPB;

    int b = blockIdx.x;
    int tid = threadIdx.x;
    int wid = tid >> 5, lane = tid & 31;
    float T2 = g_T2[b];
    float rw = reg_wt[b], gub = lgu[b];
    float gmin1 = fmaxf(1.f, gub);
    for (int i = tid; i < Mw; i += 256) {
        float lb = glb_lb[b * Mw + i] * T2;
        float ub = glb_ub[b * Mw + i] * T2;
        s_lb[i] = lb; s_w[i] = ub - lb; s_tw[i] = tw[b * Mw + i];
    }
    for (int i = tid; i < Kd; i += 256) s_frac[i] = (float)i / 95.0f;
    __syncthreads();
    // ---- per-step tables ----
    if (tid < Mw - 1) {
        int i = tid;
        float dtw = s_tw[i + 1] - s_tw[i];
        float invd = __fdividef(1.f, dtw);
        float rwd = rw * dtw;
        s_rwd[i] = rwd;
        bool unif = (s_lb[i + 1] == s_lb[i]) && (s_w[i + 1] == s_w[i]) && (gub >= 0.f);
        {
            float wp = s_w[i];
            float sinv = wp * invd * (1.0f / 95.0f);
            s_e2f[i] = edge_fn(sinv, gub, rwd);
            bool ok = unif && (wp > 0.f) && (2.f * sinv >= gmin1);
            float emin = fminf(edge_fn(-sinv, gub, rwd), edge_fn(2.f * sinv, gub, rwd));
            s_cpf[i] = ok ? (emin - 15.f - rwd) : NINFf;
        }
        {
            float wp = s_w[i + 1];
            float sinv = wp * invd * (1.0f / 95.0f);
            s_e2b[i] = edge_fn(sinv, gub, rwd);
            bool ok = unif && (wp > 0.f) && (2.f * sinv >= gmin1);
            float emin = fminf(edge_fn(-sinv, gub, rwd), edge_fn(2.f * sinv, gub, rwd));
            s_cpb[i] = ok ? (emin - 15.f - rwd) : NINFf;
        }
    }
    __syncthreads();

    int kb = 3 * lane;
    bool gl = (lane >= 1), gr = (lane <= 30);

    if (wid == 0) {
        // ======== forward scan ========
        {
            float a0 = g_node[b][0][kb], a1 = g_node[b][0][kb + 1], a2 = g_node[b][0][kb + 2];
            histA[kb] = a0; histA[kb + 1] = a1; histA[kb + 2] = a2;
            float pA0 = g_node[b][1][kb], pA1 = g_node[b][1][kb + 1], pA2 = g_node[b][1][kb + 2];
            float pB0 = g_node[b][2][kb], pB1 = g_node[b][2][kb + 1], pB2 = g_node[b][2][kb + 2];
            float pC0 = g_node[b][3][kb], pC1 = g_node[b][3][kb + 1], pC2 = g_node[b][3][kb + 2];
            float rA = s_rwd[0], eA = s_e2f[0];
            float rB = s_rwd[1], eB = s_e2f[1];
            float rC = s_rwd[2], eC = s_e2f[2];
            const float* npF = &g_node[b][4][kb];
            for (int g = 0; g < 84; g++) {
                int i = 3 * g;
                FWD_BODY(i,     pA0, pA1, pA2, rA, eA);
                FWD_BODY(i + 1, pB0, pB1, pB2, rB, eB);
                FWD_BODY(i + 2, pC0, pC1, pC2, rC, eC);
            }
            FWD_TAIL(252, pA0, pA1, pA2, rA, eA);
            FWD_TAIL(253, pB0, pB1, pB2, rB, eB);
            FWD_TAIL(254, pC0, pC1, pC2, rC, eC);
        }
        __syncwarp();
        // ======== verify vs precomputed caps ========
        bool allok = true;
        for (int s = lane; s < Mw - 1; s += 32) {
            const float4* row = (const float4*)(histA + s * HSTRIDE);
            float mn = INFf, mx = -INFf;
            #pragma unroll
            for (int q = 0; q < Kd / 4; q++) {
                float4 v = row[q];
                mn = fminf(mn, fminf(fminf(v.x, v.y), fminf(v.z, v.w)));
                mx = fmaxf(mx, fmaxf(fmaxf(v.x, v.y), fmaxf(v.z, v.w)));
            }
            allok = allok && ((mx - mn) <= s_cpf[s]);
        }
        // ======== cold general redo ========
        if (!__all_sync(FULLM, allok)) {
            float a0 = g_node[b][0][kb], a1 = g_node[b][0][kb + 1], a2 = g_node[b][0][kb + 2];
            histA[kb] = a0; histA[kb + 1] = a1; histA[kb + 2] = a2;
            float mina = o2f(__reduce_min_sync(FULLM, f2o(fminf(fminf(a0, a1), a2))));
            float maxa = o2f(__reduce_max_sync(FULLM, f2o(fmaxf(fmaxf(a0, a1), a2))));
            float lbp = s_lb[0], wp = s_w[0], twp = s_tw[0];
            float frs[3] = {(float)kb / 95.0f, (float)(kb + 1) / 95.0f, (float)(kb + 2) / 95.0f};
            for (int i = 0; i < Mw - 1; i++) {
                float lbn = s_lb[i + 1], wn = s_w[i + 1], twn = s_tw[i + 1];
                float dtw = twn - twp;
                float invd = __fdividef(1.f, dtw);
                float rwd = rw * dtw;
                s_aF[kb] = a0; s_aF[kb + 1] = a1; s_aF[kb + 2] = a2;
                __syncwarp();
                float marg = sqrta((maxa - mina + 16.f) * (1.f / BARRIERc));
                float inv95wp = __fdividef(95.0f, wp);
                bool degen = !(wp > 0.f);
                float loOff = (gub + marg) * dtw;
                float hiOff = marg * dtw;
                float res[3];
                #pragma unroll
                for (int r = 0; r < 3; r++) {
                    float tnk = lbn + wn * frs[r];
                    int jlo = max(0, __float2int_ru((tnk - loOff - lbp) * inv95wp));
                    int jhi = min(Kd - 1, __float2int_rd((tnk + hiOff - lbp) * inv95wp));
                    if (degen) { jlo = 0; jhi = Kd - 1; }
                    if (jhi < jlo) { int c = min(Kd - 1, max(0, jlo)); jlo = max(0, c - 1); jhi = min(Kd - 1, c + 1); }
                    res[r] = softmin_win(s_aF, s_frac, jlo, jhi, tnk, 1.f, invd, lbp, wp, gub, rwd);
                }
                __syncwarp();
                float an0 = g_node[b][i + 1][kb] + res[0];
                float an1 = g_node[b][i + 1][kb + 1] + res[1];
                float an2 = g_node[b][i + 1][kb + 2] + res[2];
                float* hr = histA + (i + 1) * HSTRIDE;
                hr[kb] = an0; hr[kb + 1] = an1; hr[kb + 2] = an2;
                mina = o2f(__reduce_min_sync(FULLM, f2o(fminf(fminf(an0, an1), an2))));
                maxa = o2f(__reduce_max_sync(FULLM, f2o(fmaxf(fmaxf(an0, an1), an2))));
                a0 = an0; a1 = an1; a2 = an2;
                lbp = lbn; wp = wn; twp = twn;
            }
        }
    } else if (wid == 1) {
        // ======== backward scan ========
        {
            float a0 = g_node[b][Mw - 1][kb], a1 = g_node[b][Mw - 1][kb + 1], a2 = g_node[b][Mw - 1][kb + 2];
            float* hr = histB + (Mw - 1) * HSTRIDE;
            hr[kb] = a0; hr[kb + 1] = a1; hr[kb + 2] = a2;
            float pA0 = g_node[b][Mw - 2][kb], pA1 = g_node[b][Mw - 2][kb + 1], pA2 = g_node[b][Mw - 2][kb + 2];
            float pB0 = g_node[b][Mw - 3][kb], pB1 = g_node[b][Mw - 3][kb + 1], pB2 = g_node[b][Mw - 3][kb + 2];
            float pC0 = g_node[b][Mw - 4][kb], pC1 = g_node[b][Mw - 4][kb + 1], pC2 = g_node[b][Mw - 4][kb + 2];
            float rA = s_rwd[Mw - 2], eA = s_e2b[Mw - 2];
            float rB = s_rwd[Mw - 3], eB = s_e2b[Mw - 3];
            float rC = s_rwd[Mw - 4], eC = s_e2b[Mw - 4];
            const float* npB = &g_node[b][Mw - 5][kb];
            for (int g = 0; g < 84; g++) {
                int i = Mw - 2 - 3 * g;
                BWD_BODY(i,     pA0, pA1, pA2, rA, eA);
                BWD_BODY(i - 1, pB0, pB1, pB2, rB, eB);
                BWD_BODY(i - 2, pC0, pC1, pC2, rC, eC);
            }
            BWD_TAIL(2, pA0, pA1, pA2, rA, eA);
            BWD_TAIL(1, pB0, pB1, pB2, rB, eB);
            BWD_TAIL(0, pC0, pC1, pC2, rC, eC);
        }
        __syncwarp();
        // ======== verify ========
        bool allok = true;
        for (int s = 1 + lane; s < Mw; s += 32) {
            const float4* row = (const float4*)(histB + s * HSTRIDE);
            float mn = INFf, mx = -INFf;
            #pragma unroll
            for (int q = 0; q < Kd / 4; q++) {
                float4 v = row[q];
                mn = fminf(mn, fminf(fminf(v.x, v.y), fminf(v.z, v.w)));
                mx = fmaxf(mx, fmaxf(fmaxf(v.x, v.y), fmaxf(v.z, v.w)));
            }
            allok = allok && ((mx - mn) <= s_cpb[s - 1]);
        }
        // ======== cold general redo ========
        if (!__all_sync(FULLM, allok)) {
            float a0 = g_node[b][Mw - 1][kb], a1 = g_node[b][Mw - 1][kb + 1], a2 = g_node[b][Mw - 1][kb + 2];
            float* hr = histB + (Mw - 1) * HSTRIDE;
            hr[kb] = a0; hr[kb + 1] = a1; hr[kb + 2] = a2;
            float mina = o2f(__reduce_min_sync(FULLM, f2o(fminf(fminf(a0, a1), a2))));
            float maxa = o2f(__reduce_max_sync(FULLM, f2o(fmaxf(fmaxf(a0, a1), a2))));
            float lbp = s_lb[Mw - 1], wp = s_w[Mw - 1], twp = s_tw[Mw - 1];
            float frs[3] = {(float)kb / 95.0f, (float)(kb + 1) / 95.0f, (float)(kb + 2) / 95.0f};
            for (int i = Mw - 2; i >= 0; i--) {
                float lbj = s_lb[i], wj = s_w[i], twj = s_tw[i];
                float dtw = twp - twj;
                float invd = __fdividef(1.f, dtw);
                float rwd = rw * dtw;
                s_aB[kb] = a0; s_aB[kb + 1] = a1; s_aB[kb + 2] = a2;
                __syncwarp();
                float marg = sqrta((maxa - mina + 16.f) * (1.f / BARRIERc));
                float inv95wp = __fdividef(95.0f, wp);
                bool degen = !(wp > 0.f);
                float loOff = marg * dtw;
                float hiOff = (gub + marg) * dtw;
                float res[3];
                #pragma unroll
                for (int r = 0; r < 3; r++) {
                    float tj = lbj + wj * frs[r];
                    int klo = max(0, __float2int_ru((tj - loOff - lbp) * inv95wp));
                    int khi = min(Kd - 1, __float2int_rd((tj + hiOff - lbp) * inv95wp));
                    if (degen) { klo = 0; khi = Kd - 1; }
                    if (khi < klo) { int cc = min(Kd - 1, max(0, klo)); klo = max(0, cc - 1); khi = min(Kd - 1, cc + 1); }
                    res[r] = softmin_win(s_aB, s_frac, klo, khi, tj, -1.f, invd, lbp, wp, gub, rwd);
                }
                __syncwarp();
                float c0 = g_node[b][i][kb] + res[0];
                float c1 = g_node[b][i][kb + 1] + res[1];
                float c2 = g_node[b][i][kb + 2] + res[2];
                float* hri = histB + i * HSTRIDE;
                hri[kb] = c0; hri[kb + 1] = c1; hri[kb + 2] = c2;
                mina = o2f(__reduce_min_sync(FULLM, f2o(fminf(fminf(c0, c1), c2))));
                maxa = o2f(__reduce_max_sync(FULLM, f2o(fmaxf(fmaxf(c0, c1), c2))));
                a0 = c0; a1 = c1; a2 = c2;
                lbp = lbj; wp = wj; twp = twj;
            }
        }
    }
    __syncthreads();

    // ======== output: 8 warps, v = alpha + c - node ========
    for (int m = wid; m < Mw; m += 8) {
        float lb = s_lb[m], w = s_w[m];
        const float* hA = histA + m * HSTRIDE;
        const float* hB = histB + m * HSTRIDE;
        float v[3], ta[3];
        #pragma unroll
        for (int r = 0; r < 3; r++) {
            int k = lane + 32 * r;
            v[r] = hA[k] + hB[k] - g_node[b][m][k];
            ta[r] = lb + w * ((float)k / 95.0f);
        }
        float l = fminf(fminf(v[0], v[1]), v[2]);
        float vmin = o2f(__reduce_min_sync(FULLM, f2o(l)));
        float ps = 0.f, pts = 0.f;
        #pragma unroll
        for (int r = 0; r < 3; r++) {
            float p = ex2a((vmin - v[r]) * IG2);
            ps += p;
            pts = fmaf(p, ta[r], pts);
        }
        for (int o = 16; o; o >>= 1) {
            ps += __shfl_xor_sync(FULLM, ps, o);
            pts += __shfl_xor_sync(FULLM, pts, o);
        }
        if (lane == 0) out[b * Mw + m] = pts / ps;
    }
}

extern "C" void kernel_launch(void* const* d_in, const int* in_sizes, int n_in,
                              void* d_out, int out_size) {
    const float* s1f    = (const float*)d_in[0];
    const float* s2f    = (const float*)d_in[1];
    const float* regw   = (const float*)d_in[2];
    const float* glb_lb = (const float*)d_in[3];
    const float* glb_ub = (const float*)d_in[4];
    const float* lgu    = (const float*)d_in[5];
    const float* t1     = (const float*)d_in[6];
    const float* t2     = (const float*)d_in[7];
    const float* twf    = (const float*)d_in[8];
    float* out = (float*)d_out;

    cudaFuncSetAttribute(k3_fused, cudaFuncAttributeMaxDynamicSharedMemorySize, SMEM_BYTES);

    k0_maxes<<<Bn, 256>>>(t1, t2);
    k2_node<<<dim3(Kd / 8, 8, Bn), 256>>>(s1f, s2f, glb_lb, glb_ub, twf);
    k3_fused<<<Bn, 256, SMEM_BYTES>>>(twf, regw, lgu, glb_lb, glb_ub, out);
}

// round 13
// speedup vs baseline: 2.1657x; 1.1281x over previous
#include <cuda_runtime.h>
#include <math.h>

#define Bn 32
#define N1 512
#define N2 512
#define Dd 128
#define Mw 256
#define Kd 96
#define BARRIERc 10000.0f

#define IG2 14.4269504088896f   /* log2(e)/gamma */
#define GLN2 0.069314718055995f /* gamma*ln(2)   */
#define INFf __int_as_float(0x7f800000)
#define NINFf __int_as_float(0xff800000)
#define FULLM 0xffffffffu

// dynamic smem layout (float offsets) for k3
#define HSTRIDE 100
#define O_HA 0
#define O_HB (Mw * HSTRIDE)
#define O_LB (2 * Mw * HSTRIDE)
#define O_W   (O_LB + Mw)
#define O_TW  (O_W + Mw)
#define O_FR  (O_TW + Mw)
#define O_AF  (O_FR + Kd)
#define O_AB  (O_AF + Kd)
#define O_RWD (O_AB + Kd)
#define O_E2F (O_RWD + Mw)
#define O_E2B (O_E2F + Mw)
#define O_CPF (O_E2B + Mw)
#define O_CPB (O_CPF + Mw)
#define SMEM_FLOATS (O_CPB + Mw)
#define SMEM_BYTES (SMEM_FLOATS * 4)

__device__ float g_T1[Bn], g_T2[Bn];
__device__ float g_node[Bn][Mw][Kd];

__device__ __forceinline__ float ex2a(float x) { float y; asm("ex2.approx.f32 %0, %1;" : "=f"(y) : "f"(x)); return y; }
__device__ __forceinline__ float lg2a(float x) { float y; asm("lg2.approx.f32 %0, %1;" : "=f"(y) : "f"(x)); return y; }
__device__ __forceinline__ float sqrta(float x) { float y; asm("sqrt.approx.f32 %0, %1;" : "=f"(y) : "f"(x)); return y; }

__device__ __forceinline__ unsigned f2o(float x) {
    unsigned u = __float_as_uint(x);
    return (u & 0x80000000u) ? ~u : (u | 0x80000000u);
}
__device__ __forceinline__ float o2f(unsigned v) {
    return __uint_as_float((v & 0x80000000u) ? (v ^ 0x80000000u) : ~v);
}

// ---------------- kernel 0: per-batch maxima ----------------
__global__ void k0_maxes(const float* __restrict__ t1, const float* __restrict__ t2) {
    int b = blockIdx.x, t = threadIdx.x;
    float m1 = -3.4e38f, m2 = -3.4e38f;
    for (int i = t; i < N1; i += 256) m1 = fmaxf(m1, t1[b * N1 + i]);
    for (int i = t; i < N2; i += 256) m2 = fmaxf(m2, t2[b * N2 + i]);
    __shared__ float s1[8], s2[8];
    for (int o = 16; o; o >>= 1) {
        m1 = fmaxf(m1, __shfl_xor_sync(FULLM, m1, o));
        m2 = fmaxf(m2, __shfl_xor_sync(FULLM, m2, o));
    }
    if ((t & 31) == 0) { s1[t >> 5] = m1; s2[t >> 5] = m2; }
    __syncthreads();
    if (t == 0) {
        float a = s1[0], c = s2[0];
        for (int w = 1; w < 8; w++) { a = fmaxf(a, s1[w]); c = fmaxf(c, s2[w]); }
        g_T1[b] = a; g_T2[b] = c;
    }
}

// ---------------- kernel 2: node costs (one 32-m chunk per block) ----------------
__global__ void k2_node(const float* __restrict__ s1f, const float* __restrict__ s2f,
                        const float* __restrict__ glb_lb, const float* __restrict__ glb_ub,
                        const float* __restrict__ tw) {
    int b = blockIdx.z;
    int mc = blockIdx.y * 32;
    int tid = threadIdx.x;
    int wq = tid >> 5, lane = tid & 31;
    int k = blockIdx.x * 8 + wq;
    __shared__ float s_lb[Mw], s_w[Mw], s_tw[Mw];
    __shared__ int   s_i0[32];
    __shared__ float s_w1[32];
    __shared__ float4 s_s1[32][32];
    float T1 = g_T1[b], T2 = g_T2[b];
    for (int i = tid; i < Mw; i += 256) {
        float lb = glb_lb[b * Mw + i] * T2;
        float ub = glb_ub[b * Mw + i] * T2;
        s_lb[i] = lb; s_w[i] = ub - lb; s_tw[i] = tw[b * Mw + i];
    }
    __syncthreads();
    float frk = (float)k / 95.0f;
    float invT2 = 1.f / T2, invT1 = 1.f / T1;
    const float* s2b = s2f + (size_t)b * N2 * Dd;
    const float* s1b = s1f + (size_t)b * N1 * Dd;
    int i0p = -1;
    float4 f0v = make_float4(0.f, 0.f, 0.f, 0.f), f1v = f0v;

    if (tid < 32) {
        float pos = s_tw[mc + tid] * invT1;
        float x = fminf(fmaxf(pos, 0.f), 1.f) * (float)(N1 - 1);
        int i0 = min(max((int)x, 0), N1 - 2);
        s_i0[tid] = i0;
        s_w1[tid] = x - (float)i0;
    }
    __syncthreads();
    for (int idx = tid; idx < 1024; idx += 256) {
        int ml = idx >> 5, l4 = idx & 31;
        const float4* r0 = (const float4*)(s1b + (size_t)s_i0[ml] * Dd);
        float4 f0 = r0[l4], f1 = r0[32 + l4];
        float ww = s_w1[ml];
        float4 o;
        o.x = f0.x + ww * (f1.x - f0.x);
        o.y = f0.y + ww * (f1.y - f0.y);
        o.z = f0.z + ww * (f1.z - f0.z);
        o.w = f0.w + ww * (f1.w - f0.w);
        s_s1[ml][l4] = o;
    }
    __syncthreads();
    for (int m0 = 0; m0 < 32; m0 += 4) {
        float acc[4], tks[4];
        #pragma unroll
        for (int u = 0; u < 4; u++) {
            int m = mc + m0 + u;
            float tk = s_lb[m] + s_w[m] * frk;
            tks[u] = tk;
            float x = fminf(fmaxf(tk * invT2, 0.f), 1.f) * (float)(N2 - 1);
            int i0 = min(max((int)x, 0), N2 - 2);
            float w = x - (float)i0;
            if (i0 != i0p) {
                f0v = *((const float4*)(s2b + (size_t)i0 * Dd) + lane);
                f1v = *((const float4*)(s2b + (size_t)(i0 + 1) * Dd) + lane);
                i0p = i0;
            }
            float4 s1v = s_s1[m0 + u][lane];
            float d0 = s1v.x - (f0v.x + w * (f1v.x - f0v.x));
            float d1 = s1v.y - (f0v.y + w * (f1v.y - f0v.y));
            float d2 = s1v.z - (f0v.z + w * (f1v.z - f0v.z));
            float d3 = s1v.w - (f0v.w + w * (f1v.w - f0v.w));
            acc[u] = fmaf(d0, d0, fmaf(d1, d1, fmaf(d2, d2, d3 * d3)));
        }
        for (int o = 16; o; o >>= 1) {
            #pragma unroll
            for (int u = 0; u < 4; u++)
                acc[u] += __shfl_xor_sync(FULLM, acc[u], o);
        }
        if (lane == 0) {
            #pragma unroll
            for (int u = 0; u < 4; u++) {
                int m = mc + m0 + u;
                float twm = s_tw[m];
                float wt = 0.f;
                if (m > 0) wt += twm - s_tw[m - 1];
                if (m < Mw - 1) wt += s_tw[m + 1] - twm;
                wt *= 0.5f;
                float node = acc[u] * wt;
                float tk = tks[u];
                if (m == 0) node += BARRIERc * tk * tk;
                if (m == Mw - 1) { float dd = tk - T2; node += BARRIERc * dd * dd; }
                g_node[b][m][k] = node;
            }
        }
    }
}

// ---------------- edge cost ----------------
__device__ __forceinline__ float edge_fn(float slope, float gub, float rwd) {
    float d1 = slope - 1.f;
    float n1 = fminf(slope, 0.f);
    float r2 = fmaxf(slope - gub, 0.f);
    float pen = fmaf(n1, n1, r2 * r2);
    return fmaf(BARRIERc, pen, rwd * d1 * d1);
}

// general windowed softmin (cold path)
__device__ __forceinline__ float softmin_win(
    const float* sa, const float* sfrac,
    int jlo, int jhi, float tref, float sgn, float invd,
    float lbp, float wp, float gub, float rwd) {
    float mval = INFf, ssum = 0.f;
    for (int j = jlo; j <= jhi; j++) {
        float tpj = lbp + wp * sfrac[j];
        float slope = sgn * (tref - tpj) * invd;
        float e = edge_fn(slope, gub, rwd);
        float xv = sa[j] + e;
        float dlt = xv - mval;
        float tt = ex2a(-fabsf(dlt) * IG2);
        if (dlt < 0.f) { ssum = fmaf(ssum, tt, 1.f); mval = xv; }
        else           { ssum += tt; }
    }
    return mval - GLN2 * lg2a(ssum);
}

// 2-candidate softmin (y may be INF), fused final fma
__device__ __forceinline__ float sm2(float x, float y) {
    float mv = fminf(x, y);
    float ss = 1.f + ex2a(-fabsf(x - y) * IG2);
    return fmaf(-GLN2, lg2a(ss), mv);
}

// fwd step: node comes from smem history row (in-place); reload slot from row i+4
#define FWD_BODY(i, NN0, NN1, NN2, RWD, E2)                                \
{                                                                          \
    float p2 = __shfl_up_sync(FULLM, a2, 1);                               \
    float an0 = NN0 + sm2(a0 + RWD, gl ? p2 + E2 : INFf);                  \
    float an1 = NN1 + sm2(a1 + RWD, a0 + E2);                              \
    float an2 = NN2 + sm2(a2 + RWD, a1 + E2);                              \
    float* hr = histA + ((i) + 1) * HSTRIDE;                               \
    hr[kb] = an0; hr[kb + 1] = an1; hr[kb + 2] = an2;                      \
    a0 = an0; a1 = an1; a2 = an2;                                          \
    const float* nr = histA + ((i) + 4) * HSTRIDE;                         \
    NN0 = nr[kb]; NN1 = nr[kb + 1]; NN2 = nr[kb + 2];                      \
    int tnx = min((i) + 3, Mw - 2);                                        \
    RWD = s_rwd[tnx]; E2 = s_e2f[tnx];                                     \
}
#define FWD_TAIL(i, NN0, NN1, NN2, RWD, E2)                                \
{                                                                          \
    float p2 = __shfl_up_sync(FULLM, a2, 1);                               \
    float an0 = NN0 + sm2(a0 + RWD, gl ? p2 + E2 : INFf);                  \
    float an1 = NN1 + sm2(a1 + RWD, a0 + E2);                              \
    float an2 = NN2 + sm2(a2 + RWD, a1 + E2);                              \
    float* hr = histA + ((i) + 1) * HSTRIDE;                               \
    hr[kb] = an0; hr[kb + 1] = an1; hr[kb + 2] = an2;                      \
    a0 = an0; a1 = an1; a2 = an2;                                          \
}

// bwd step: node from histB row i (in-place); reload slot from row i-3
#define BWD_BODY(i, NI0, NI1, NI2, RWD, E2)                                \
{                                                                          \
    float n0 = __shfl_down_sync(FULLM, a0, 1);                             \
    float bn0 = sm2(a0 + RWD, a1 + E2);                                    \
    float bn1 = sm2(a1 + RWD, a2 + E2);                                    \
    float bn2 = sm2(a2 + RWD, gr ? n0 + E2 : INFf);                        \
    float c0 = NI0 + bn0, c1 = NI1 + bn1, c2 = NI2 + bn2;                  \
    float* hri = histB + (i) * HSTRIDE;                                    \
    hri[kb] = c0; hri[kb + 1] = c1; hri[kb + 2] = c2;                      \
    a0 = c0; a1 = c1; a2 = c2;                                             \
    const float* nr = histB + ((i) - 3) * HSTRIDE;                         \
    NI0 = nr[kb]; NI1 = nr[kb + 1]; NI2 = nr[kb + 2];                      \
    int tnx = max((i) - 3, 0);                                             \
    RWD = s_rwd[tnx]; E2 = s_e2b[tnx];                                     \
}
#define BWD_TAIL(i, NI0, NI1, NI2, RWD, E2)                                \
{                                                                          \
    float n0 = __shfl_down_sync(FULLM, a0, 1);                             \
    float bn0 = sm2(a0 + RWD, a1 + E2);                                    \
    float bn1 = sm2(a1 + RWD, a2 + E2);                                    \
    float bn2 = sm2(a2 + RWD, gr ? n0 + E2 : INFf);                        \
    float c0 = NI0 + bn0, c1 = NI1 + bn1, c2 = NI2 + bn2;                  \
    float* hri = histB + (i) * HSTRIDE;                                    \
    hri[kb] = c0; hri[kb + 1] = c1; hri[kb + 2] = c2;                      \
    a0 = c0; a1 = c1; a2 = c2;                                             \
}

// ---------------- kernel 3: fused scans, node preloaded into smem history ----------------
__global__ void k3_fused(const float* __restrict__ tw, const float* __restrict__ reg_wt,
                         const float* __restrict__ lgu, const float* __restrict__ glb_lb,
                         const float* __restrict__ glb_ub, float* __restrict__ out) {
    extern __shared__ float sm[];
    float* histA = sm + O_HA;
    float* histB = sm + O_HB;
    float* s_lb  = sm + O_LB;
    float* s_w   = sm + O_W;
    float* s_tw  = sm + O_TW;
    float* s_frac= sm + O_FR;
    float* s_aF  = sm + O_AF;
    float* s_aB  = sm + O_AB;
    float* s_rwd = sm + O_RWD;
    float* s_e2f = sm + O_E2F;
    float* s_e2b = sm + O_E2B;
    float* s_cpf = sm + O_CPF;
    float* s_cpb = sm + O_CPB;

    int b = blockIdx.x;
    int tid = threadIdx.x;
    int wid = tid >> 5, lane = tid & 31;
    float T2 = g_T2[b];
    float rw = reg_wt[b], gub = lgu[b];
    float gmin1 = fmaxf(1.f, gub);
    for (int i = tid; i < Mw; i += 256) {
        float lb = glb_lb[b * Mw + i] * T2;
        float ub = glb_ub[b * Mw + i] * T2;
        s_lb[i] = lb; s_w[i] = ub - lb; s_tw[i] = tw[b * Mw + i];
    }
    for (int i = tid; i < Kd; i += 256) s_frac[i] = (float)i / 95.0f;
    // ---- preload node into both history buffers (float4, coalesced) ----
    {
        const float4* gn4 = (const float4*)&g_node[b][0][0];
        for (int idx = tid; idx < (Mw * Kd) / 4; idx += 256) {
            int m = idx / (Kd / 4), j = idx % (Kd / 4);
            float4 v = gn4[idx];
            *(float4*)(histA + m * HSTRIDE + 4 * j) = v;
            *(float4*)(histB + m * HSTRIDE + 4 * j) = v;
        }
    }
    __syncthreads();
    // ---- per-step tables ----
    if (tid < Mw - 1) {
        int i = tid;
        float dtw = s_tw[i + 1] - s_tw[i];
        float invd = __fdividef(1.f, dtw);
        float rwd = rw * dtw;
        s_rwd[i] = rwd;
        bool unif = (s_lb[i + 1] == s_lb[i]) && (s_w[i + 1] == s_w[i]) && (gub >= 0.f);
        {
            float wp = s_w[i];
            float sinv = wp * invd * (1.0f / 95.0f);
            s_e2f[i] = edge_fn(sinv, gub, rwd);
            bool ok = unif && (wp > 0.f) && (2.f * sinv >= gmin1);
            float emin = fminf(edge_fn(-sinv, gub, rwd), edge_fn(2.f * sinv, gub, rwd));
            s_cpf[i] = ok ? (emin - 15.f - rwd) : NINFf;
        }
        {
            float wp = s_w[i + 1];
            float sinv = wp * invd * (1.0f / 95.0f);
            s_e2b[i] = edge_fn(sinv, gub, rwd);
            bool ok = unif && (wp > 0.f) && (2.f * sinv >= gmin1);
            float emin = fminf(edge_fn(-sinv, gub, rwd), edge_fn(2.f * sinv, gub, rwd));
            s_cpb[i] = ok ? (emin - 15.f - rwd) : NINFf;
        }
    }
    __syncthreads();

    int kb = 3 * lane;
    bool gl = (lane >= 1), gr = (lane <= 30);

    if (wid == 0) {
        // ======== forward scan (all-smem) ========
        {
            float a0 = histA[kb], a1 = histA[kb + 1], a2 = histA[kb + 2];
            const float* r1 = histA + 1 * HSTRIDE;
            const float* r2 = histA + 2 * HSTRIDE;
            const float* r3 = histA + 3 * HSTRIDE;
            float pA0 = r1[kb], pA1 = r1[kb + 1], pA2 = r1[kb + 2];
            float pB0 = r2[kb], pB1 = r2[kb + 1], pB2 = r2[kb + 2];
            float pC0 = r3[kb], pC1 = r3[kb + 1], pC2 = r3[kb + 2];
            float rA = s_rwd[0], eA = s_e2f[0];
            float rB = s_rwd[1], eB = s_e2f[1];
            float rC = s_rwd[2], eC = s_e2f[2];
            for (int g = 0; g < 84; g++) {
                int i = 3 * g;
                FWD_BODY(i,     pA0, pA1, pA2, rA, eA);
                FWD_BODY(i + 1, pB0, pB1, pB2, rB, eB);
                FWD_BODY(i + 2, pC0, pC1, pC2, rC, eC);
            }
            FWD_TAIL(252, pA0, pA1, pA2, rA, eA);
            FWD_TAIL(253, pB0, pB1, pB2, rB, eB);
            FWD_TAIL(254, pC0, pC1, pC2, rC, eC);
        }
        __syncwarp();
        // ======== verify vs precomputed caps ========
        bool allok = true;
        for (int s = lane; s < Mw - 1; s += 32) {
            const float4* row = (const float4*)(histA + s * HSTRIDE);
            float mn = INFf, mx = -INFf;
            #pragma unroll
            for (int q = 0; q < Kd / 4; q++) {
                float4 v = row[q];
                mn = fminf(mn, fminf(fminf(v.x, v.y), fminf(v.z, v.w)));
                mx = fmaxf(mx, fmaxf(fmaxf(v.x, v.y), fmaxf(v.z, v.w)));
            }
            allok = allok && ((mx - mn) <= s_cpf[s]);
        }
        // ======== cold general redo (reads pristine g_node) ========
        if (!__all_sync(FULLM, allok)) {
            float a0 = g_node[b][0][kb], a1 = g_node[b][0][kb + 1], a2 = g_node[b][0][kb + 2];
            histA[kb] = a0; histA[kb + 1] = a1; histA[kb + 2] = a2;
            float mina = o2f(__reduce_min_sync(FULLM, f2o(fminf(fminf(a0, a1), a2))));
            float maxa = o2f(__reduce_max_sync(FULLM, f2o(fmaxf(fmaxf(a0, a1), a2))));
            float lbp = s_lb[0], wp = s_w[0], twp = s_tw[0];
            float frs[3] = {(float)kb / 95.0f, (float)(kb + 1) / 95.0f, (float)(kb + 2) / 95.0f};
            for (int i = 0; i < Mw - 1; i++) {
                float lbn = s_lb[i + 1], wn = s_w[i + 1], twn = s_tw[i + 1];
                float dtw = twn - twp;
                float invd = __fdividef(1.f, dtw);
                float rwd = rw * dtw;
                s_aF[kb] = a0; s_aF[kb + 1] = a1; s_aF[kb + 2] = a2;
                __syncwarp();
                float marg = sqrta((maxa - mina + 16.f) * (1.f / BARRIERc));
                float inv95wp = __fdividef(95.0f, wp);
                bool degen = !(wp > 0.f);
                float loOff = (gub + marg) * dtw;
                float hiOff = marg * dtw;
                float res[3];
                #pragma unroll
                for (int r = 0; r < 3; r++) {
                    float tnk = lbn + wn * frs[r];
                    int jlo = max(0, __float2int_ru((tnk - loOff - lbp) * inv95wp));
                    int jhi = min(Kd - 1, __float2int_rd((tnk + hiOff - lbp) * inv95wp));
                    if (degen) { jlo = 0; jhi = Kd - 1; }
                    if (jhi < jlo) { int c = min(Kd - 1, max(0, jlo)); jlo = max(0, c - 1); jhi = min(Kd - 1, c + 1); }
                    res[r] = softmin_win(s_aF, s_frac, jlo, jhi, tnk, 1.f, invd, lbp, wp, gub, rwd);
                }
                __syncwarp();
                float an0 = g_node[b][i + 1][kb] + res[0];
                float an1 = g_node[b][i + 1][kb + 1] + res[1];
                float an2 = g_node[b][i + 1][kb + 2] + res[2];
                float* hr = histA + (i + 1) * HSTRIDE;
                hr[kb] = an0; hr[kb + 1] = an1; hr[kb + 2] = an2;
                mina = o2f(__reduce_min_sync(FULLM, f2o(fminf(fminf(an0, an1), an2))));
                maxa = o2f(__reduce_max_sync(FULLM, f2o(fmaxf(fmaxf(an0, an1), an2))));
                a0 = an0; a1 = an1; a2 = an2;
                lbp = lbn; wp = wn; twp = twn;
            }
        }
    } else if (wid == 1) {
        // ======== backward scan (all-smem) ========
        {
            const float* rT = histB + (Mw - 1) * HSTRIDE;
            float a0 = rT[kb], a1 = rT[kb + 1], a2 = rT[kb + 2];
            const float* r1 = histB + (Mw - 2) * HSTRIDE;
            const float* r2 = histB + (Mw - 3) * HSTRIDE;
            const float* r3 = histB + (Mw - 4) * HSTRIDE;
            float pA0 = r1[kb], pA1 = r1[kb + 1], pA2 = r1[kb + 2];
            float pB0 = r2[kb], pB1 = r2[kb + 1], pB2 = r2[kb + 2];
            float pC0 = r3[kb], pC1 = r3[kb + 1], pC2 = r3[kb + 2];
            float rA = s_rwd[Mw - 2], eA = s_e2b[Mw - 2];
            float rB = s_rwd[Mw - 3], eB = s_e2b[Mw - 3];
            float rC = s_rwd[Mw - 4], eC = s_e2b[Mw - 4];
            for (int g = 0; g < 84; g++) {
                int i = Mw - 2 - 3 * g;
                BWD_BODY(i,     pA0, pA1, pA2, rA, eA);
                BWD_BODY(i - 1, pB0, pB1, pB2, rB, eB);
                BWD_BODY(i - 2, pC0, pC1, pC2, rC, eC);
            }
            BWD_TAIL(2, pA0, pA1, pA2, rA, eA);
            BWD_TAIL(1, pB0, pB1, pB2, rB, eB);
            BWD_TAIL(0, pC0, pC1, pC2, rC, eC);
        }
        __syncwarp();
        // ======== verify ========
        bool allok = true;
        for (int s = 1 + lane; s < Mw; s += 32) {
            const float4* row = (const float4*)(histB + s * HSTRIDE);
            float mn = INFf, mx = -INFf;
            #pragma unroll
            for (int q = 0; q < Kd / 4; q++) {
                float4 v = row[q];
                mn = fminf(mn, fminf(fminf(v.x, v.y), fminf(v.z, v.w)));
                mx = fmaxf(mx, fmaxf(fmaxf(v.x, v.y), fmaxf(v.z, v.w)));
            }
            allok = allok && ((mx - mn) <= s_cpb[s - 1]);
        }
        // ======== cold general redo ========
        if (!__all_sync(FULLM, allok)) {
            float a0 = g_node[b][Mw - 1][kb], a1 = g_node[b][Mw - 1][kb + 1], a2 = g_node[b][Mw - 1][kb + 2];
            float* hr = histB + (Mw - 1) * HSTRIDE;
            hr[kb] = a0; hr[kb + 1] = a1; hr[kb + 2] = a2;
            float mina = o2f(__reduce_min_sync(FULLM, f2o(fminf(fminf(a0, a1), a2))));
            float maxa = o2f(__reduce_max_sync(FULLM, f2o(fmaxf(fmaxf(a0, a1), a2))));
            float lbp = s_lb[Mw - 1], wp = s_w[Mw - 1], twp = s_tw[Mw - 1];
            float frs[3] = {(float)kb / 95.0f, (float)(kb + 1) / 95.0f, (float)(kb + 2) / 95.0f};
            for (int i = Mw - 2; i >= 0; i--) {
                float lbj = s_lb[i], wj = s_w[i], twj = s_tw[i];
                float dtw = twp - twj;
                float invd = __fdividef(1.f, dtw);
                float rwd = rw * dtw;
                s_aB[kb] = a0; s_aB[kb + 1] = a1; s_aB[kb + 2] = a2;
                __syncwarp();
                float marg = sqrta((maxa - mina + 16.f) * (1.f / BARRIERc));
                float inv95wp = __fdividef(95.0f, wp);
                bool degen = !(wp > 0.f);
                float loOff = marg * dtw;
                float hiOff = (gub + marg) * dtw;
                float res[3];
                #pragma unroll
                for (int r = 0; r < 3; r++) {
                    float tj = lbj + wj * frs[r];
                    int klo = max(0, __float2int_ru((tj - loOff - lbp) * inv95wp));
                    int khi = min(Kd - 1, __float2int_rd((tj + hiOff - lbp) * inv95wp));
                    if (degen) { klo = 0; khi = Kd - 1; }
                    if (khi < klo) { int cc = min(Kd - 1, max(0, klo)); klo = max(0, cc - 1); khi = min(Kd - 1, cc + 1); }
                    res[r] = softmin_win(s_aB, s_frac, klo, khi, tj, -1.f, invd, lbp, wp, gub, rwd);
                }
                __syncwarp();
                float c0 = g_node[b][i][kb] + res[0];
                float c1 = g_node[b][i][kb + 1] + res[1];
                float c2 = g_node[b][i][kb + 2] + res[2];
                float* hri = histB + i * HSTRIDE;
                hri[kb] = c0; hri[kb + 1] = c1; hri[kb + 2] = c2;
                mina = o2f(__reduce_min_sync(FULLM, f2o(fminf(fminf(c0, c1), c2))));
                maxa = o2f(__reduce_max_sync(FULLM, f2o(fmaxf(fmaxf(c0, c1), c2))));
                a0 = c0; a1 = c1; a2 = c2;
                lbp = lbj; wp = wj; twp = twj;
            }
        }
    }
    __syncthreads();

    // ======== output: 8 warps, v = alpha + c - node ========
    for (int m = wid; m < Mw; m += 8) {
        float lb = s_lb[m], w = s_w[m];
        const float* hA = histA + m * HSTRIDE;
        const float* hB = histB + m * HSTRIDE;
        float v[3], ta[3];
        #pragma unroll
        for (int r = 0; r < 3; r++) {
            int k = lane + 32 * r;
            v[r] = hA[k] + hB[k] - g_node[b][m][k];
            ta[r] = lb + w * ((float)k / 95.0f);
        }
        float l = fminf(fminf(v[0], v[1]), v[2]);
        float vmin = o2f(__reduce_min_sync(FULLM, f2o(l)));
        float ps = 0.f, pts = 0.f;
        #pragma unroll
        for (int r = 0; r < 3; r++) {
            float p = ex2a((vmin - v[r]) * IG2);
            ps += p;
            pts = fmaf(p, ta[r], pts);
        }
        for (int o = 16; o; o >>= 1) {
            ps += __shfl_xor_sync(FULLM, ps, o);
            pts += __shfl_xor_sync(FULLM, pts, o);
        }
        if (lane == 0) out[b * Mw + m] = pts / ps;
    }
}

extern "C" void kernel_launch(void* const* d_in, const int* in_sizes, int n_in,
                              void* d_out, int out_size) {
    const float* s1f    = (const float*)d_in[0];
    const float* s2f    = (const float*)d_in[1];
    const float* regw   = (const float*)d_in[2];
    const float* glb_lb = (const float*)d_in[3];
    const float* glb_ub = (const float*)d_in[4];
    const float* lgu    = (const float*)d_in[5];
    const float* t1     = (const float*)d_in[6];
    const float* t2     = (const float*)d_in[7];
    const float* twf    = (const float*)d_in[8];
    float* out = (float*)d_out;

    cudaFuncSetAttribute(k3_fused, cudaFuncAttributeMaxDynamicSharedMemorySize, SMEM_BYTES);

    k0_maxes<<<Bn, 256>>>(t1, t2);
    k2_node<<<dim3(Kd / 8, 8, Bn), 256>>>(s1f, s2f, glb_lb, glb_ub, twf);
    k3_fused<<<Bn, 256, SMEM_BYTES>>>(twf, regw, lgu, glb_lb, glb_ub, out);
}

// round 14
// speedup vs baseline: 2.2208x; 1.0254x over previous
#include <cuda_runtime.h>
#include <math.h>

#define Bn 32
#define N1 512
#define N2 512
#define Dd 128
#define Mw 256
#define Kd 96
#define BARRIERc 10000.0f

#define IG2 14.4269504088896f   /* log2(e)/gamma */
#define GLN2 0.069314718055995f /* gamma*ln(2)   */
#define INFf __int_as_float(0x7f800000)
#define NINFf __int_as_float(0xff800000)
#define FULLM 0xffffffffu

// dynamic smem layout (float offsets) for k3
#define HSTRIDE 100
#define O_HA 0
#define O_HB (Mw * HSTRIDE)
#define O_LB (2 * Mw * HSTRIDE)
#define O_W   (O_LB + Mw)
#define O_TW  (O_W + Mw)
#define O_FR  (O_TW + Mw)
#define O_AF  (O_FR + Kd)
#define O_AB  (O_AF + Kd)
#define O_RWD (O_AB + Kd)
#define O_E2F (O_RWD + Mw)
#define O_E2B (O_E2F + Mw)
#define O_CPF (O_E2B + Mw)
#define O_CPB (O_CPF + Mw)
#define O_SC  (O_CPB + Mw)
#define SMEM_FLOATS (O_SC + 16)
#define SMEM_BYTES (SMEM_FLOATS * 4)

__device__ float g_node[Bn][Mw][Kd];

__device__ __forceinline__ float ex2a(float x) { float y; asm("ex2.approx.f32 %0, %1;" : "=f"(y) : "f"(x)); return y; }
__device__ __forceinline__ float lg2a(float x) { float y; asm("lg2.approx.f32 %0, %1;" : "=f"(y) : "f"(x)); return y; }
__device__ __forceinline__ float sqrta(float x) { float y; asm("sqrt.approx.f32 %0, %1;" : "=f"(y) : "f"(x)); return y; }

__device__ __forceinline__ unsigned f2o(float x) {
    unsigned u = __float_as_uint(x);
    return (u & 0x80000000u) ? ~u : (u | 0x80000000u);
}
__device__ __forceinline__ float o2f(unsigned v) {
    return __uint_as_float((v & 0x80000000u) ? (v ^ 0x80000000u) : ~v);
}

// combined block-wide maxes of two arrays (512 each), 256 threads, one sync
__device__ __forceinline__ void block_max2(const float* __restrict__ p1, const float* __restrict__ p2,
                                           float* scratch, float& out1, float& out2) {
    int tid = threadIdx.x;
    float m1 = -3.4e38f, m2 = -3.4e38f;
    #pragma unroll
    for (int r = 0; r < 2; r++) {
        m1 = fmaxf(m1, p1[tid + 256 * r]);
        m2 = fmaxf(m2, p2[tid + 256 * r]);
    }
    for (int o = 16; o; o >>= 1) {
        m1 = fmaxf(m1, __shfl_xor_sync(FULLM, m1, o));
        m2 = fmaxf(m2, __shfl_xor_sync(FULLM, m2, o));
    }
    if ((tid & 31) == 0) { scratch[tid >> 5] = m1; scratch[8 + (tid >> 5)] = m2; }
    __syncthreads();
    float a = scratch[0], c = scratch[8];
    #pragma unroll
    for (int w = 1; w < 8; w++) { a = fmaxf(a, scratch[w]); c = fmaxf(c, scratch[8 + w]); }
    out1 = a; out2 = c;
}

// ---------------- kernel 2: node costs (24 k-values per block, fused maxes) ----------------
__global__ void k2_node(const float* __restrict__ s1f, const float* __restrict__ s2f,
                        const float* __restrict__ glb_lb, const float* __restrict__ glb_ub,
                        const float* __restrict__ tw, const float* __restrict__ t1g,
                        const float* __restrict__ t2g) {
    int b = blockIdx.z;
    int mc = blockIdx.y * 32;
    int kg = blockIdx.x * 24;
    int tid = threadIdx.x;
    int wq = tid >> 5, lane = tid & 31;
    __shared__ float s_lb[Mw], s_w[Mw], s_tw[Mw];
    __shared__ int   s_i0[32];
    __shared__ float s_w1[32];
    __shared__ float4 s_s1[32][32];
    __shared__ float sc[16];
    float T1, T2;
    block_max2(t1g + b * N1, t2g + b * N2, sc, T1, T2);
    for (int i = tid; i < Mw; i += 256) {
        float lb = glb_lb[b * Mw + i] * T2;
        float ub = glb_ub[b * Mw + i] * T2;
        s_lb[i] = lb; s_w[i] = ub - lb; s_tw[i] = tw[b * Mw + i];
    }
    __syncthreads();
    float invT2 = 1.f / T2, invT1 = 1.f / T1;
    const float* s2b = s2f + (size_t)b * N2 * Dd;
    const float* s1b = s1f + (size_t)b * N1 * Dd;

    if (tid < 32) {
        float pos = s_tw[mc + tid] * invT1;
        float x = fminf(fmaxf(pos, 0.f), 1.f) * (float)(N1 - 1);
        int i0 = min(max((int)x, 0), N1 - 2);
        s_i0[tid] = i0;
        s_w1[tid] = x - (float)i0;
    }
    __syncthreads();
    for (int idx = tid; idx < 1024; idx += 256) {
        int ml = idx >> 5, l4 = idx & 31;
        const float4* r0 = (const float4*)(s1b + (size_t)s_i0[ml] * Dd);
        float4 f0 = r0[l4], f1 = r0[32 + l4];
        float ww = s_w1[ml];
        float4 o;
        o.x = f0.x + ww * (f1.x - f0.x);
        o.y = f0.y + ww * (f1.y - f0.y);
        o.z = f0.z + ww * (f1.z - f0.z);
        o.w = f0.w + ww * (f1.w - f0.w);
        s_s1[ml][l4] = o;
    }
    __syncthreads();
    for (int kj = 0; kj < 3; kj++) {
        int k = kg + kj * 8 + wq;
        float frk = (float)k / 95.0f;
        int i0p = -1;
        float4 f0v = make_float4(0.f, 0.f, 0.f, 0.f), f1v = f0v;
        for (int m0 = 0; m0 < 32; m0 += 4) {
            float acc[4], tks[4];
            #pragma unroll
            for (int u = 0; u < 4; u++) {
                int m = mc + m0 + u;
                float tk = s_lb[m] + s_w[m] * frk;
                tks[u] = tk;
                float x = fminf(fmaxf(tk * invT2, 0.f), 1.f) * (float)(N2 - 1);
                int i0 = min(max((int)x, 0), N2 - 2);
                float w = x - (float)i0;
                if (i0 != i0p) {
                    f0v = *((const float4*)(s2b + (size_t)i0 * Dd) + lane);
                    f1v = *((const float4*)(s2b + (size_t)(i0 + 1) * Dd) + lane);
                    i0p = i0;
                }
                float4 s1v = s_s1[m0 + u][lane];
                float d0 = s1v.x - (f0v.x + w * (f1v.x - f0v.x));
                float d1 = s1v.y - (f0v.y + w * (f1v.y - f0v.y));
                float d2 = s1v.z - (f0v.z + w * (f1v.z - f0v.z));
                float d3 = s1v.w - (f0v.w + w * (f1v.w - f0v.w));
                acc[u] = fmaf(d0, d0, fmaf(d1, d1, fmaf(d2, d2, d3 * d3)));
            }
            for (int o = 16; o; o >>= 1) {
                #pragma unroll
                for (int u = 0; u < 4; u++)
                    acc[u] += __shfl_xor_sync(FULLM, acc[u], o);
            }
            if (lane == 0) {
                #pragma unroll
                for (int u = 0; u < 4; u++) {
                    int m = mc + m0 + u;
                    float twm = s_tw[m];
                    float wt = 0.f;
                    if (m > 0) wt += twm - s_tw[m - 1];
                    if (m < Mw - 1) wt += s_tw[m + 1] - twm;
                    wt *= 0.5f;
                    float node = acc[u] * wt;
                    float tk = tks[u];
                    if (m == 0) node += BARRIERc * tk * tk;
                    if (m == Mw - 1) { float dd = tk - T2; node += BARRIERc * dd * dd; }
                    g_node[b][m][k] = node;
                }
            }
        }
    }
}

// ---------------- edge cost ----------------
__device__ __forceinline__ float edge_fn(float slope, float gub, float rwd) {
    float d1 = slope - 1.f;
    float n1 = fminf(slope, 0.f);
    float r2 = fmaxf(slope - gub, 0.f);
    float pen = fmaf(n1, n1, r2 * r2);
    return fmaf(BARRIERc, pen, rwd * d1 * d1);
}

// general windowed softmin (cold path)
__device__ __forceinline__ float softmin_win(
    const float* sa, const float* sfrac,
    int jlo, int jhi, float tref, float sgn, float invd,
    float lbp, float wp, float gub, float rwd) {
    float mval = INFf, ssum = 0.f;
    for (int j = jlo; j <= jhi; j++) {
        float tpj = lbp + wp * sfrac[j];
        float slope = sgn * (tref - tpj) * invd;
        float e = edge_fn(slope, gub, rwd);
        float xv = sa[j] + e;
        float dlt = xv - mval;
        float tt = ex2a(-fabsf(dlt) * IG2);
        if (dlt < 0.f) { ssum = fmaf(ssum, tt, 1.f); mval = xv; }
        else           { ssum += tt; }
    }
    return mval - GLN2 * lg2a(ssum);
}

// 2-candidate softmin (y may be INF), fused final fma
__device__ __forceinline__ float sm2(float x, float y) {
    float mv = fminf(x, y);
    float ss = 1.f + ex2a(-fabsf(x - y) * IG2);
    return fmaf(-GLN2, lg2a(ss), mv);
}

// fwd step: node comes from smem history row (in-place); reload slot from row i+4
#define FWD_BODY(i, NN0, NN1, NN2, RWD, E2)                                \
{                                                                          \
    float p2 = __shfl_up_sync(FULLM, a2, 1);                               \
    float an0 = NN0 + sm2(a0 + RWD, gl ? p2 + E2 : INFf);                  \
    float an1 = NN1 + sm2(a1 + RWD, a0 + E2);                              \
    float an2 = NN2 + sm2(a2 + RWD, a1 + E2);                              \
    float* hr = histA + ((i) + 1) * HSTRIDE;                               \
    hr[kb] = an0; hr[kb + 1] = an1; hr[kb + 2] = an2;                      \
    a0 = an0; a1 = an1; a2 = an2;                                          \
    const float* nr = histA + ((i) + 4) * HSTRIDE;                         \
    NN0 = nr[kb]; NN1 = nr[kb + 1]; NN2 = nr[kb + 2];                      \
    int tnx = min((i) + 3, Mw - 2);                                        \
    RWD = s_rwd[tnx]; E2 = s_e2f[tnx];                                     \
}
#define FWD_TAIL(i, NN0, NN1, NN2, RWD, E2)                                \
{                                                                          \
    float p2 = __shfl_up_sync(FULLM, a2, 1);                               \
    float an0 = NN0 + sm2(a0 + RWD, gl ? p2 + E2 : INFf);                  \
    float an1 = NN1 + sm2(a1 + RWD, a0 + E2);                              \
    float an2 = NN2 + sm2(a2 + RWD, a1 + E2);                              \
    float* hr = histA + ((i) + 1) * HSTRIDE;                               \
    hr[kb] = an0; hr[kb + 1] = an1; hr[kb + 2] = an2;                      \
    a0 = an0; a1 = an1; a2 = an2;                                          \
}

// bwd step: node from histB row i (in-place); reload slot from row i-3
#define BWD_BODY(i, NI0, NI1, NI2, RWD, E2)                                \
{                                                                          \
    float n0 = __shfl_down_sync(FULLM, a0, 1);                             \
    float bn0 = sm2(a0 + RWD, a1 + E2);                                    \
    float bn1 = sm2(a1 + RWD, a2 + E2);                                    \
    float bn2 = sm2(a2 + RWD, gr ? n0 + E2 : INFf);                        \
    float c0 = NI0 + bn0, c1 = NI1 + bn1, c2 = NI2 + bn2;                  \
    float* hri = histB + (i) * HSTRIDE;                                    \
    hri[kb] = c0; hri[kb + 1] = c1; hri[kb + 2] = c2;                      \
    a0 = c0; a1 = c1; a2 = c2;                                             \
    const float* nr = histB + ((i) - 3) * HSTRIDE;                         \
    NI0 = nr[kb]; NI1 = nr[kb + 1]; NI2 = nr[kb + 2];                      \
    int tnx = max((i) - 3, 0);                                             \
    RWD = s_rwd[tnx]; E2 = s_e2b[tnx];                                     \
}
#define BWD_TAIL(i, NI0, NI1, NI2, RWD, E2)                                \
{                                                                          \
    float n0 = __shfl_down_sync(FULLM, a0, 1);                             \
    float bn0 = sm2(a0 + RWD, a1 + E2);                                    \
    float bn1 = sm2(a1 + RWD, a2 + E2);                                    \
    float bn2 = sm2(a2 + RWD, gr ? n0 + E2 : INFf);                        \
    float c0 = NI0 + bn0, c1 = NI1 + bn1, c2 = NI2 + bn2;                  \
    float* hri = histB + (i) * HSTRIDE;                                    \
    hri[kb] = c0; hri[kb + 1] = c1; hri[kb + 2] = c2;                      \
    a0 = c0; a1 = c1; a2 = c2;                                             \
}

// ---------------- kernel 3: fused scans, node preloaded into smem history ----------------
__global__ void k3_fused(const float* __restrict__ tw, const float* __restrict__ reg_wt,
                         const float* __restrict__ lgu, const float* __restrict__ glb_lb,
                         const float* __restrict__ glb_ub, const float* __restrict__ t2g,
                         float* __restrict__ out) {
    extern __shared__ float sm[];
    float* histA = sm + O_HA;
    float* histB = sm + O_HB;
    float* s_lb  = sm + O_LB;
    float* s_w   = sm + O_W;
    float* s_tw  = sm + O_TW;
    float* s_frac= sm + O_FR;
    float* s_aF  = sm + O_AF;
    float* s_aB  = sm + O_AB;
    float* s_rwd = sm + O_RWD;
    float* s_e2f = sm + O_E2F;
    float* s_e2b = sm + O_E2B;
    float* s_cpf = sm + O_CPF;
    float* s_cpb = sm + O_CPB;
    float* s_sc  = sm + O_SC;

    int b = blockIdx.x;
    int tid = threadIdx.x;
    int wid = tid >> 5, lane = tid & 31;
    float T2, Tdummy;
    block_max2(t2g + b * N2, t2g + b * N2, s_sc, T2, Tdummy);
    float rw = reg_wt[b], gub = lgu[b];
    float gmin1 = fmaxf(1.f, gub);
    for (int i = tid; i < Mw; i += 256) {
        float lb = glb_lb[b * Mw + i] * T2;
        float ub = glb_ub[b * Mw + i] * T2;
        s_lb[i] = lb; s_w[i] = ub - lb; s_tw[i] = tw[b * Mw + i];
    }
    for (int i = tid; i < Kd; i += 256) s_frac[i] = (float)i / 95.0f;
    // ---- preload node into both history buffers ----
    {
        const float4* gn4 = (const float4*)&g_node[b][0][0];
        for (int idx = tid; idx < (Mw * Kd) / 4; idx += 256) {
            int m = idx / (Kd / 4), j = idx % (Kd / 4);
            float4 v = gn4[idx];
            *(float4*)(histA + m * HSTRIDE + 4 * j) = v;
            *(float4*)(histB + m * HSTRIDE + 4 * j) = v;
        }
    }
    __syncthreads();
    // ---- per-step tables ----
    if (tid < Mw - 1) {
        int i = tid;
        float dtw = s_tw[i + 1] - s_tw[i];
        float invd = __fdividef(1.f, dtw);
        float rwd = rw * dtw;
        s_rwd[i] = rwd;
        bool unif = (s_lb[i + 1] == s_lb[i]) && (s_w[i + 1] == s_w[i]) && (gub >= 0.f);
        {
            float wp = s_w[i];
            float sinv = wp * invd * (1.0f / 95.0f);
            s_e2f[i] = edge_fn(sinv, gub, rwd);
            bool ok = unif && (wp > 0.f) && (2.f * sinv >= gmin1);
            float emin = fminf(edge_fn(-sinv, gub, rwd), edge_fn(2.f * sinv, gub, rwd));
            s_cpf[i] = ok ? (emin - 15.f - rwd) : NINFf;
        }
        {
            float wp = s_w[i + 1];
            float sinv = wp * invd * (1.0f / 95.0f);
            s_e2b[i] = edge_fn(sinv, gub, rwd);
            bool ok = unif && (wp > 0.f) && (2.f * sinv >= gmin1);
            float emin = fminf(edge_fn(-sinv, gub, rwd), edge_fn(2.f * sinv, gub, rwd));
            s_cpb[i] = ok ? (emin - 15.f - rwd) : NINFf;
        }
    }
    __syncthreads();

    int kb = 3 * lane;
    bool gl = (lane >= 1), gr = (lane <= 30);

    if (wid == 0) {
        // ======== forward scan (all-smem) ========
        {
            float a0 = histA[kb], a1 = histA[kb + 1], a2 = histA[kb + 2];
            const float* r1 = histA + 1 * HSTRIDE;
            const float* r2 = histA + 2 * HSTRIDE;
            const float* r3 = histA + 3 * HSTRIDE;
            float pA0 = r1[kb], pA1 = r1[kb + 1], pA2 = r1[kb + 2];
            float pB0 = r2[kb], pB1 = r2[kb + 1], pB2 = r2[kb + 2];
            float pC0 = r3[kb], pC1 = r3[kb + 1], pC2 = r3[kb + 2];
            float rA = s_rwd[0], eA = s_e2f[0];
            float rB = s_rwd[1], eB = s_e2f[1];
            float rC = s_rwd[2], eC = s_e2f[2];
            for (int g = 0; g < 84; g++) {
                int i = 3 * g;
                FWD_BODY(i,     pA0, pA1, pA2, rA, eA);
                FWD_BODY(i + 1, pB0, pB1, pB2, rB, eB);
                FWD_BODY(i + 2, pC0, pC1, pC2, rC, eC);
            }
            FWD_TAIL(252, pA0, pA1, pA2, rA, eA);
            FWD_TAIL(253, pB0, pB1, pB2, rB, eB);
            FWD_TAIL(254, pC0, pC1, pC2, rC, eC);
        }
        __syncwarp();
        // ======== verify vs precomputed caps ========
        bool allok = true;
        for (int s = lane; s < Mw - 1; s += 32) {
            const float4* row = (const float4*)(histA + s * HSTRIDE);
            float mn = INFf, mx = -INFf;
            #pragma unroll
            for (int q = 0; q < Kd / 4; q++) {
                float4 v = row[q];
                mn = fminf(mn, fminf(fminf(v.x, v.y), fminf(v.z, v.w)));
                mx = fmaxf(mx, fmaxf(fmaxf(v.x, v.y), fmaxf(v.z, v.w)));
            }
            allok = allok && ((mx - mn) <= s_cpf[s]);
        }
        // ======== cold general redo (reads pristine g_node) ========
        if (!__all_sync(FULLM, allok)) {
            float a0 = g_node[b][0][kb], a1 = g_node[b][0][kb + 1], a2 = g_node[b][0][kb + 2];
            histA[kb] = a0; histA[kb + 1] = a1; histA[kb + 2] = a2;
            float mina = o2f(__reduce_min_sync(FULLM, f2o(fminf(fminf(a0, a1), a2))));
            float maxa = o2f(__reduce_max_sync(FULLM, f2o(fmaxf(fmaxf(a0, a1), a2))));
            float lbp = s_lb[0], wp = s_w[0], twp = s_tw[0];
            float frs[3] = {(float)kb / 95.0f, (float)(kb + 1) / 95.0f, (float)(kb + 2) / 95.0f};
            for (int i = 0; i < Mw - 1; i++) {
                float lbn = s_lb[i + 1], wn = s_w[i + 1], twn = s_tw[i + 1];
                float dtw = twn - twp;
                float invd = __fdividef(1.f, dtw);
                float rwd = rw * dtw;
                s_aF[kb] = a0; s_aF[kb + 1] = a1; s_aF[kb + 2] = a2;
                __syncwarp();
                float marg = sqrta((maxa - mina + 16.f) * (1.f / BARRIERc));
                float inv95wp = __fdividef(95.0f, wp);
                bool degen = !(wp > 0.f);
                float loOff = (gub + marg) * dtw;
                float hiOff = marg * dtw;
                float res[3];
                #pragma unroll
                for (int r = 0; r < 3; r++) {
                    float tnk = lbn + wn * frs[r];
                    int jlo = max(0, __float2int_ru((tnk - loOff - lbp) * inv95wp));
                    int jhi = min(Kd - 1, __float2int_rd((tnk + hiOff - lbp) * inv95wp));
                    if (degen) { jlo = 0; jhi = Kd - 1; }
                    if (jhi < jlo) { int c = min(Kd - 1, max(0, jlo)); jlo = max(0, c - 1); jhi = min(Kd - 1, c + 1); }
                    res[r] = softmin_win(s_aF, s_frac, jlo, jhi, tnk, 1.f, invd, lbp, wp, gub, rwd);
                }
                __syncwarp();
                float an0 = g_node[b][i + 1][kb] + res[0];
                float an1 = g_node[b][i + 1][kb + 1] + res[1];
                float an2 = g_node[b][i + 1][kb + 2] + res[2];
                float* hr = histA + (i + 1) * HSTRIDE;
                hr[kb] = an0; hr[kb + 1] = an1; hr[kb + 2] = an2;
                mina = o2f(__reduce_min_sync(FULLM, f2o(fminf(fminf(an0, an1), an2))));
                maxa = o2f(__reduce_max_sync(FULLM, f2o(fmaxf(fmaxf(an0, an1), an2))));
                a0 = an0; a1 = an1; a2 = an2;
                lbp = lbn; wp = wn; twp = twn;
            }
        }
    } else if (wid == 1) {
        // ======== backward scan (all-smem) ========
        {
            const float* rT = histB + (Mw - 1) * HSTRIDE;
            float a0 = rT[kb], a1 = rT[kb + 1], a2 = rT[kb + 2];
            const float* r1 = histB + (Mw - 2) * HSTRIDE;
            const float* r2 = histB + (Mw - 3) * HSTRIDE;
            const float* r3 = histB + (Mw - 4) * HSTRIDE;
            float pA0 = r1[kb], pA1 = r1[kb + 1], pA2 = r1[kb + 2];
            float pB0 = r2[kb], pB1 = r2[kb + 1], pB2 = r2[kb + 2];
            float pC0 = r3[kb], pC1 = r3[kb + 1], pC2 = r3[kb + 2];
            float rA = s_rwd[Mw - 2], eA = s_e2b[Mw - 2];
            float rB = s_rwd[Mw - 3], eB = s_e2b[Mw - 3];
            float rC = s_rwd[Mw - 4], eC = s_e2b[Mw - 4];
            for (int g = 0; g < 84; g++) {
                int i = Mw - 2 - 3 * g;
                BWD_BODY(i,     pA0, pA1, pA2, rA, eA);
                BWD_BODY(i - 1, pB0, pB1, pB2, rB, eB);
                BWD_BODY(i - 2, pC0, pC1, pC2, rC, eC);
            }
            BWD_TAIL(2, pA0, pA1, pA2, rA, eA);
            BWD_TAIL(1, pB0, pB1, pB2, rB, eB);
            BWD_TAIL(0, pC0, pC1, pC2, rC, eC);
        }
        __syncwarp();
        // ======== verify ========
        bool allok = true;
        for (int s = 1 + lane; s < Mw; s += 32) {
            const float4* row = (const float4*)(histB + s * HSTRIDE);
            float mn = INFf, mx = -INFf;
            #pragma unroll
            for (int q = 0; q < Kd / 4; q++) {
                float4 v = row[q];
                mn = fminf(mn, fminf(fminf(v.x, v.y), fminf(v.z, v.w)));
                mx = fmaxf(mx, fmaxf(fmaxf(v.x, v.y), fmaxf(v.z, v.w)));
            }
            allok = allok && ((mx - mn) <= s_cpb[s - 1]);
        }
        // ======== cold general redo ========
        if (!__all_sync(FULLM, allok)) {
            float a0 = g_node[b][Mw - 1][kb], a1 = g_node[b][Mw - 1][kb + 1], a2 = g_node[b][Mw - 1][kb + 2];
            float* hr = histB + (Mw - 1) * HSTRIDE;
            hr[kb] = a0; hr[kb + 1] = a1; hr[kb + 2] = a2;
            float mina = o2f(__reduce_min_sync(FULLM, f2o(fminf(fminf(a0, a1), a2))));
            float maxa = o2f(__reduce_max_sync(FULLM, f2o(fmaxf(fmaxf(a0, a1), a2))));
            float lbp = s_lb[Mw - 1], wp = s_w[Mw - 1], twp = s_tw[Mw - 1];
            float frs[3] = {(float)kb / 95.0f, (float)(kb + 1) / 95.0f, (float)(kb + 2) / 95.0f};
            for (int i = Mw - 2; i >= 0; i--) {
                float lbj = s_lb[i], wj = s_w[i], twj = s_tw[i];
                float dtw = twp - twj;
                float invd = __fdividef(1.f, dtw);
                float rwd = rw * dtw;
                s_aB[kb] = a0; s_aB[kb + 1] = a1; s_aB[kb + 2] = a2;
                __syncwarp();
                float marg = sqrta((maxa - mina + 16.f) * (1.f / BARRIERc));
                float inv95wp = __fdividef(95.0f, wp);
                bool degen = !(wp > 0.f);
                float loOff = marg * dtw;
                float hiOff = (gub + marg) * dtw;
                float res[3];
                #pragma unroll
                for (int r = 0; r < 3; r++) {
                    float tj = lbj + wj * frs[r];
                    int klo = max(0, __float2int_ru((tj - loOff - lbp) * inv95wp));
                    int khi = min(Kd - 1, __float2int_rd((tj + hiOff - lbp) * inv95wp));
                    if (degen) { klo = 0; khi = Kd - 1; }
                    if (khi < klo) { int cc = min(Kd - 1, max(0, klo)); klo = max(0, cc - 1); khi = min(Kd - 1, cc + 1); }
                    res[r] = softmin_win(s_aB, s_frac, klo, khi, tj, -1.f, invd, lbp, wp, gub, rwd);
                }
                __syncwarp();
                float c0 = g_node[b][i][kb] + res[0];
                float c1 = g_node[b][i][kb + 1] + res[1];
                float c2 = g_node[b][i][kb + 2] + res[2];
                float* hri = histB + i * HSTRIDE;
                hri[kb] = c0; hri[kb + 1] = c1; hri[kb + 2] = c2;
                mina = o2f(__reduce_min_sync(FULLM, f2o(fminf(fminf(c0, c1), c2))));
                maxa = o2f(__reduce_max_sync(FULLM, f2o(fmaxf(fmaxf(c0, c1), c2))));
                a0 = c0; a1 = c1; a2 = c2;
                lbp = lbj; wp = wj; twp = twj;
            }
        }
    }
    __syncthreads();

    // ======== output: 8 warps, v = alpha + c - node ========
    for (int m = wid; m < Mw; m += 8) {
        float lb = s_lb[m], w = s_w[m];
        const float* hA = histA + m * HSTRIDE;
        const float* hB = histB + m * HSTRIDE;
        float v[3], ta[3];
        #pragma unroll
        for (int r = 0; r < 3; r++) {
            int k = lane + 32 * r;
            v[r] = hA[k] + hB[k] - g_node[b][m][k];
            ta[r] = lb + w * ((float)k / 95.0f);
        }
        float l = fminf(fminf(v[0], v[1]), v[2]);
        float vmin = o2f(__reduce_min_sync(FULLM, f2o(l)));
        float ps = 0.f, pts = 0.f;
        #pragma unroll
        for (int r = 0; r < 3; r++) {
            float p = ex2a((vmin - v[r]) * IG2);
            ps += p;
            pts = fmaf(p, ta[r], pts);
        }
        for (int o = 16; o; o >>= 1) {
            ps += __shfl_xor_sync(FULLM, ps, o);
            pts += __shfl_xor_sync(FULLM, pts, o);
        }
        if (lane == 0) out[b * Mw + m] = pts / ps;
    }
}

extern "C" void kernel_launch(void* const* d_in, const int* in_sizes, int n_in,
                              void* d_out, int out_size) {
    const float* s1f    = (const float*)d_in[0];
    const float* s2f    = (const float*)d_in[1];
    const float* regw   = (const float*)d_in[2];
    const float* glb_lb = (const float*)d_in[3];
    const float* glb_ub = (const float*)d_in[4];
    const float* lgu    = (const float*)d_in[5];
    const float* t1     = (const float*)d_in[6];
    const float* t2     = (const float*)d_in[7];
    const float* twf    = (const float*)d_in[8];
    float* out = (float*)d_out;

    cudaFuncSetAttribute(k3_fused, cudaFuncAttributeMaxDynamicSharedMemorySize, SMEM_BYTES);

    k2_node<<<dim3(4, 8, Bn), 256>>>(s1f, s2f, glb_lb, glb_ub, twf, t1, t2);
    k3_fused<<<Bn, 256, SMEM_BYTES>>>(twf, regw, lgu, glb_lb, glb_ub, t2, out);
}